// round 3
// baseline (speedup 1.0000x reference)
#include <cuda_runtime.h>
#include <cuda_bf16.h>

// ---------------------------------------------------------------------------
// Net_80796924772492: small permuted-group CNN, B=64.
// Pipeline: dw1(5x5,g=3) -> permgroup1(+relu+pool) -> dw2(5x5,g=51)
//        -> permgroup2(+relu+pool) -> 1x1 conv 515->100 (+relu, flatten)
//        -> fc1(2500->120,relu) -> fc2(120->84,relu) -> fc3(84->10)
// ---------------------------------------------------------------------------

#define BATCH 64

// ---- intermediate buffers (device globals: no allocation allowed) ----------
__device__ float g_buf1[BATCH * 18 * 28 * 28];   // dw1 out
__device__ float g_buf2[BATCH * 51 * 14 * 14];   // pc1+relu+pool out
__device__ float g_buf3[BATCH * 255 * 10 * 10];  // dw2 out
__device__ float g_buf4[BATCH * 515 * 5 * 5];    // pc2+relu+pool out
__device__ float g_buf5[BATCH * 2500];           // oo out (flattened)
__device__ float g_buf6[BATCH * 120];            // fc1 out

// per-group info: (j, rep = i*ncpf+j, base = k*ncpf, 0)
__device__ int4 g_g1info[51];
__device__ int4 g_g2info[515];

// ---------------------------------------------------------------------------
// Init: derive per-group (i,j,k) from build_perm's enumeration order.
// For filter index i: j==0 contributes (F-i) groups (k = i..F-1),
// then j = 1..ncpf-1 each contributes (F-1-i) groups (k = i+1..F-1).
// ---------------------------------------------------------------------------
__device__ __forceinline__ int4 group_info(int g, int F, int ncpf) {
    int rem = g;
    int i = 0;
    for (;;) {
        int cnt = (F - i) + (ncpf - 1) * (F - 1 - i);
        if (rem < cnt) break;
        rem -= cnt;
        i++;
    }
    int j, k;
    if (rem < F - i) {
        j = 0;
        k = i + rem;
    } else {
        rem -= (F - i);
        j = 1 + rem / (F - 1 - i);
        k = i + 1 + rem % (F - 1 - i);
    }
    int4 r;
    r.x = j;
    r.y = i * ncpf + j;  // replacement channel
    r.z = k * ncpf;      // base of donor block
    r.w = 0;
    return r;
}

__global__ void init_groupinfo_kernel() {
    int g = blockIdx.x * blockDim.x + threadIdx.x;
    if (g < 51) {
        g_g1info[g] = group_info(g, 6, 3);
    } else if (g < 51 + 515) {
        g_g2info[g - 51] = group_info(g - 51, 5, 51);
    }
}

// ---------------------------------------------------------------------------
// dw1: x[64,3,32,32] -> [64,18,28,28], 5x5 depthwise-grouped (g=3, 6 out/grp)
// ---------------------------------------------------------------------------
__global__ void dw1_kernel(const float* __restrict__ x,
                           const float* __restrict__ w,
                           const float* __restrict__ bias) {
    int idx = blockIdx.x * blockDim.x + threadIdx.x;
    if (idx >= BATCH * 18 * 28 * 28) return;
    int xo = idx % 28;
    int t = idx / 28;
    int yo = t % 28; t /= 28;
    int o = t % 18;
    int b = t / 18;
    int ci = o / 6;
    const float* xp = x + (((b * 3 + ci) * 32 + yo) * 32 + xo);
    const float* wp = w + o * 25;
    float acc = bias[o];
#pragma unroll
    for (int ky = 0; ky < 5; ky++)
#pragma unroll
        for (int kx = 0; kx < 5; kx++)
            acc = fmaf(xp[ky * 32 + kx], __ldg(wp + ky * 5 + kx), acc);
    g_buf1[idx] = acc;
}

// ---------------------------------------------------------------------------
// pc1 (grouped 1x1 over 3 permuted channels) + relu + 2x2 maxpool
// in: g_buf1 [64,18,28,28]  out: g_buf2 [64,51,14,14]
// ---------------------------------------------------------------------------
__global__ void pc1pool_kernel(const float* __restrict__ w,
                               const float* __restrict__ bias) {
    int idx = blockIdx.x * blockDim.x + threadIdx.x;
    if (idx >= BATCH * 51 * 14 * 14) return;
    int px = idx % 14;
    int t = idx / 14;
    int py = t % 14; t /= 14;
    int g = t % 51;
    int b = t / 51;

    int4 gi = g_g1info[g];
    int ch0 = (gi.x == 0) ? gi.y : gi.z + 0;
    int ch1 = (gi.x == 1) ? gi.y : gi.z + 1;
    int ch2 = (gi.x == 2) ? gi.y : gi.z + 2;

    const float* base = g_buf1 + b * 18 * 784;
    const float* p0 = base + ch0 * 784;
    const float* p1 = base + ch1 * 784;
    const float* p2 = base + ch2 * 784;

    float w0 = __ldg(w + g * 3 + 0);
    float w1 = __ldg(w + g * 3 + 1);
    float w2 = __ldg(w + g * 3 + 2);
    float bb = __ldg(bias + g);

    float m = 0.0f;  // max of relus == max(0, raw values)
#pragma unroll
    for (int dy = 0; dy < 2; dy++) {
#pragma unroll
        for (int dx = 0; dx < 2; dx++) {
            int off = (2 * py + dy) * 28 + (2 * px + dx);
            float v = bb;
            v = fmaf(w0, p0[off], v);
            v = fmaf(w1, p1[off], v);
            v = fmaf(w2, p2[off], v);
            m = fmaxf(m, v);
        }
    }
    g_buf2[idx] = m;
}

// ---------------------------------------------------------------------------
// dw2: [64,51,14,14] -> [64,255,10,10], 5x5 grouped (g=51, 5 out/grp)
// ---------------------------------------------------------------------------
__global__ void dw2_kernel(const float* __restrict__ w,
                           const float* __restrict__ bias) {
    int idx = blockIdx.x * blockDim.x + threadIdx.x;
    if (idx >= BATCH * 255 * 100) return;
    int xo = idx % 10;
    int t = idx / 10;
    int yo = t % 10; t /= 10;
    int o = t % 255;
    int b = t / 255;
    int ci = o / 5;
    const float* xp = g_buf2 + ((b * 51 + ci) * 196 + yo * 14 + xo);
    const float* wp = w + o * 25;
    float acc = bias[o];
#pragma unroll
    for (int ky = 0; ky < 5; ky++)
#pragma unroll
        for (int kx = 0; kx < 5; kx++)
            acc = fmaf(xp[ky * 14 + kx], __ldg(wp + ky * 5 + kx), acc);
    g_buf3[idx] = acc;
}

// ---------------------------------------------------------------------------
// pc2 (grouped 1x1 over 51 permuted channels) + relu + 2x2 maxpool
// in: g_buf3 [64,255,10,10]  out: g_buf4 [64,515,5,5]
// block = (b, pooled row py); smem holds 255 channels x 2 rows x 10 cols.
// ---------------------------------------------------------------------------
__global__ void pc2pool_kernel(const float* __restrict__ w,
                               const float* __restrict__ bias) {
    __shared__ float s[255 * 20];  // 20.4 KB
    int b = blockIdx.x / 5;
    int py = blockIdx.x % 5;

    const float* src = g_buf3 + b * 25500 + (2 * py) * 10;  // chan stride 100
    for (int i = threadIdx.x; i < 255 * 20; i += blockDim.x) {
        int ch = i / 20;
        int off = i % 20;                 // r*10 + c
        s[i] = src[ch * 100 + (off / 10) * 10 + (off % 10)];
    }
    __syncthreads();

    for (int o = threadIdx.x; o < 515 * 5; o += blockDim.x) {
        int g = o / 5;
        int px = o % 5;
        int4 gi = g_g2info[g];
        int j = gi.x, rep = gi.y, base = gi.z;
        const float* wr = w + g * 51;
        float bb = __ldg(bias + g);
        float v00 = bb, v01 = bb, v10 = bb, v11 = bb;
        int c2 = 2 * px;
#pragma unroll 3
        for (int c = 0; c < 51; c++) {
            int ch = (c == j) ? rep : base + c;
            float ww = __ldg(wr + c);
            const float* sp = s + ch * 20 + c2;
            v00 = fmaf(ww, sp[0], v00);
            v01 = fmaf(ww, sp[1], v01);
            v10 = fmaf(ww, sp[10], v10);
            v11 = fmaf(ww, sp[11], v11);
        }
        float m = fmaxf(fmaxf(v00, v01), fmaxf(v10, v11));
        m = fmaxf(m, 0.0f);
        g_buf4[(b * 515 + g) * 25 + py * 5 + px] = m;
    }
}

// ---------------------------------------------------------------------------
// oo: 1x1 conv 515->100 over 5x5, +bias, +relu; output stored flattened
// [b, oc*25 + pix] matching reference reshape order.
// block = (b, quarter of output channels); input tile in dynamic smem.
// ---------------------------------------------------------------------------
__global__ void oo_kernel(const float* __restrict__ w,
                          const float* __restrict__ bias) {
    extern __shared__ float s[];  // 515*25 floats = 51.5 KB
    int b = blockIdx.x >> 2;
    int q = blockIdx.x & 3;
    const float* src = g_buf4 + b * 515 * 25;
    for (int i = threadIdx.x; i < 515 * 25; i += blockDim.x) s[i] = src[i];
    __syncthreads();

    for (int o = q * 625 + threadIdx.x; o < (q + 1) * 625; o += blockDim.x) {
        int oc = o / 25;
        int pix = o % 25;
        const float* wr = w + oc * 515;
        float acc = __ldg(bias + oc);
#pragma unroll 5
        for (int c = 0; c < 515; c++)
            acc = fmaf(__ldg(wr + c), s[c * 25 + pix], acc);
        g_buf5[b * 2500 + o] = fmaxf(acc, 0.0f);
    }
}

// ---------------------------------------------------------------------------
// fc1: [64,2500] x [2500,120]^T + bias, relu. Warp per output, float4 loads.
// ---------------------------------------------------------------------------
__global__ void fc1_kernel(const float* __restrict__ w,
                           const float* __restrict__ bias) {
    int wid = (blockIdx.x * blockDim.x + threadIdx.x) >> 5;
    int lane = threadIdx.x & 31;
    if (wid >= BATCH * 120) return;
    int b = wid / 120;
    int o = wid % 120;
    const float4* in = reinterpret_cast<const float4*>(g_buf5 + b * 2500);
    const float4* wr = reinterpret_cast<const float4*>(w + o * 2500);
    float acc = 0.0f;
    for (int i = lane; i < 625; i += 32) {
        float4 a = in[i];
        float4 ww = __ldg(wr + i);
        acc = fmaf(a.x, ww.x, acc);
        acc = fmaf(a.y, ww.y, acc);
        acc = fmaf(a.z, ww.z, acc);
        acc = fmaf(a.w, ww.w, acc);
    }
#pragma unroll
    for (int off = 16; off; off >>= 1)
        acc += __shfl_xor_sync(0xffffffffu, acc, off);
    if (lane == 0) g_buf6[wid] = fmaxf(acc + __ldg(bias + o), 0.0f);
}

// ---------------------------------------------------------------------------
// fc2 (relu) + fc3 fused. block per batch element.
// ---------------------------------------------------------------------------
__global__ void fc_tail_kernel(const float* __restrict__ w2,
                               const float* __restrict__ b2,
                               const float* __restrict__ w3,
                               const float* __restrict__ b3,
                               float* __restrict__ out) {
    __shared__ float h1[120];
    __shared__ float h2[84];
    int b = blockIdx.x;
    int t = threadIdx.x;
    if (t < 120) h1[t] = g_buf6[b * 120 + t];
    __syncthreads();
    if (t < 84) {
        float acc = __ldg(b2 + t);
        const float* wr = w2 + t * 120;
#pragma unroll 4
        for (int c = 0; c < 120; c++) acc = fmaf(__ldg(wr + c), h1[c], acc);
        h2[t] = fmaxf(acc, 0.0f);
    }
    __syncthreads();
    if (t < 10) {
        float acc = __ldg(b3 + t);
        const float* wr = w3 + t * 84;
#pragma unroll 4
        for (int c = 0; c < 84; c++) acc = fmaf(__ldg(wr + c), h2[c], acc);
        out[b * 10 + t] = acc;
    }
}

// ---------------------------------------------------------------------------
extern "C" void kernel_launch(void* const* d_in, const int* in_sizes, int n_in,
                              void* d_out, int out_size) {
    const float* x     = (const float*)d_in[0];
    const float* dw1_w = (const float*)d_in[1];
    const float* dw1_b = (const float*)d_in[2];
    const float* pc1_w = (const float*)d_in[3];
    const float* pc1_b = (const float*)d_in[4];
    const float* dw2_w = (const float*)d_in[5];
    const float* dw2_b = (const float*)d_in[6];
    const float* pc2_w = (const float*)d_in[7];
    const float* pc2_b = (const float*)d_in[8];
    const float* oo_w  = (const float*)d_in[9];
    const float* oo_b  = (const float*)d_in[10];
    const float* fc1_w = (const float*)d_in[11];
    const float* fc1_b = (const float*)d_in[12];
    const float* fc2_w = (const float*)d_in[13];
    const float* fc2_b = (const float*)d_in[14];
    const float* fc3_w = (const float*)d_in[15];
    const float* fc3_b = (const float*)d_in[16];
    float* out = (float*)d_out;

    // opt-in >48KB dynamic smem for oo_kernel (idempotent, not a stream op)
    static bool attr_set = false;
    if (!attr_set) {
        cudaFuncSetAttribute(oo_kernel,
                             cudaFuncAttributeMaxDynamicSharedMemorySize,
                             515 * 25 * (int)sizeof(float));
        attr_set = true;
    }

    init_groupinfo_kernel<<<3, 256>>>();

    {
        int n = BATCH * 18 * 28 * 28;
        dw1_kernel<<<(n + 255) / 256, 256>>>(x, dw1_w, dw1_b);
    }
    {
        int n = BATCH * 51 * 14 * 14;
        pc1pool_kernel<<<(n + 255) / 256, 256>>>(pc1_w, pc1_b);
    }
    {
        int n = BATCH * 255 * 100;
        dw2_kernel<<<(n + 255) / 256, 256>>>(dw2_w, dw2_b);
    }
    pc2pool_kernel<<<BATCH * 5, 256>>>(pc2_w, pc2_b);
    oo_kernel<<<BATCH * 4, 256, 515 * 25 * sizeof(float)>>>(oo_w, oo_b);
    {
        int warps = BATCH * 120;                 // one warp per output
        int threads = warps * 32;
        fc1_kernel<<<(threads + 255) / 256, 256>>>(fc1_w, fc1_b);
    }
    fc_tail_kernel<<<BATCH, 128>>>(fc2_w, fc2_b, fc3_w, fc3_b, out);
}

// round 4
// speedup vs baseline: 2.2221x; 2.2221x over previous
#include <cuda_runtime.h>
#include <cuda_bf16.h>

// ---------------------------------------------------------------------------
// Net_80796924772492: small permuted-group CNN, B=64.
// dw1(5x5,g=3) -> pc1(+relu+pool) -> dw2(5x5,g=51) -> pc2(+relu+pool)
//  -> 1x1 515->100 (+relu) -> fc1 -> fc2 -> fc3
// ---------------------------------------------------------------------------

#define BATCH 64

__device__ float g_buf1[BATCH * 18 * 28 * 28];   // dw1 out
__device__ float g_buf2[BATCH * 51 * 14 * 14];   // pc1+relu+pool out
__device__ float g_buf3[BATCH * 255 * 10 * 10];  // dw2 out
__device__ float g_buf4[BATCH * 515 * 25];       // pc2+relu+pool out
__device__ float g_buf5[BATCH * 2500];           // oo out (flattened)
__device__ float g_buf6[BATCH * 120];            // fc1 out

// pc1 per-group info: (j, rep = i*ncpf+j, base = k*ncpf, 0)
__device__ int4 g_g1info[51];
// pc2 groups sorted by k, padded to quads of 4 (same k within a quad):
// slot -> (g, j, rep = i*51+j, base = k*51). 131 quads = 524 slots.
__device__ int4 g_g2sorted[524];

// ---------------------------------------------------------------------------
__device__ __forceinline__ int4 group_info(int g, int F, int ncpf) {
    int rem = g;
    int i = 0;
    for (;;) {
        int cnt = (F - i) + (ncpf - 1) * (F - 1 - i);
        if (rem < cnt) break;
        rem -= cnt;
        i++;
    }
    int j, k;
    if (rem < F - i) { j = 0; k = i + rem; }
    else {
        rem -= (F - i);
        j = 1 + rem / (F - 1 - i);
        k = i + 1 + rem % (F - 1 - i);
    }
    int4 r; r.x = j; r.y = i * ncpf + j; r.z = k * ncpf; r.w = 0;
    return r;
}

__global__ void init_groupinfo_kernel() {
    int t = blockIdx.x * blockDim.x + threadIdx.x;
    if (t < 51) {
        g_g1info[t] = group_info(t, 6, 3);
    } else if (t < 51 + 524) {
        int s = t - 51;
        // quad-count prefix per k: G_k = {1,52,103,154,205} -> quads {1,13,26,39,52}
        const int qs[6] = {0, 1, 14, 40, 79, 131};
        const int Gk[5] = {1, 52, 103, 154, 205};
        int q = s >> 2;
        int k = 0;
        while (k < 4 && q >= qs[k + 1]) k++;
        int r = s - qs[k] * 4;
        if (r > Gk[k] - 1) r = Gk[k] - 1;   // pad: replicate last group
        int i, j;
        if (r <= k) { i = r; j = 0; }
        else { int r2 = r - (k + 1); i = r2 / 50; j = 1 + r2 % 50; }
        // original group id: prefix over i' < i of cnt(i') = 205 - 51*i'
        int base_i = 205 * i - 51 * (i * (i - 1) / 2);
        int off = (j == 0) ? (k - i)
                           : (5 - i) + (j - 1) * (4 - i) + (k - i - 1);
        int4 v; v.x = base_i + off; v.y = j; v.z = i * 51 + j; v.w = k * 51;
        g_g2sorted[s] = v;
    }
}

// ---------------------------------------------------------------------------
// dw1: x[64,3,32,32] -> [64,18,28,28]. Block=(b,ci), 32x32 tile in smem,
// thread computes a 14-wide x-strip with register row reuse.
// ---------------------------------------------------------------------------
__global__ void dw1_kernel(const float* __restrict__ x,
                           const float* __restrict__ w,
                           const float* __restrict__ bias) {
    __shared__ float s[32 * 33];
    int b = blockIdx.x / 3, ci = blockIdx.x % 3;
    int tid = threadIdx.x;
    const float* src = x + (b * 3 + ci) * 1024;
    for (int i = tid; i < 1024; i += 256)
        s[(i >> 5) * 33 + (i & 31)] = src[i];
    __syncthreads();

    for (int u = tid; u < 336; u += 256) {   // 6 oc * 28 yo * 2 halves
        int oc6 = u / 56, rest = u % 56;
        int yo = rest >> 1, xh = rest & 1;
        int o = ci * 6 + oc6;
        const float* wp = w + o * 25;
        float bb = __ldg(bias + o);
        float acc[14];
#pragma unroll
        for (int t = 0; t < 14; t++) acc[t] = bb;
        for (int ky = 0; ky < 5; ky++) {
            int rb = (yo + ky) * 33 + xh * 14;
            float r[18];
#pragma unroll
            for (int t = 0; t < 18; t++) r[t] = s[rb + t];
#pragma unroll
            for (int kx = 0; kx < 5; kx++) {
                float ww = __ldg(wp + ky * 5 + kx);
#pragma unroll
                for (int xo = 0; xo < 14; xo++)
                    acc[xo] = fmaf(r[xo + kx], ww, acc[xo]);
            }
        }
        float* dst = g_buf1 + ((b * 18 + o) * 28 + yo) * 28 + xh * 14;
#pragma unroll
        for (int t = 0; t < 14; t++) dst[t] = acc[t];
    }
}

// ---------------------------------------------------------------------------
// pc1 (grouped 1x1 over 3 permuted channels) + relu + 2x2 maxpool
// ---------------------------------------------------------------------------
__global__ void pc1pool_kernel(const float* __restrict__ w,
                               const float* __restrict__ bias) {
    int idx = blockIdx.x * blockDim.x + threadIdx.x;
    if (idx >= BATCH * 51 * 14 * 14) return;
    int px = idx % 14;
    int t = idx / 14;
    int py = t % 14; t /= 14;
    int g = t % 51;
    int b = t / 51;

    int4 gi = g_g1info[g];
    int ch0 = (gi.x == 0) ? gi.y : gi.z + 0;
    int ch1 = (gi.x == 1) ? gi.y : gi.z + 1;
    int ch2 = (gi.x == 2) ? gi.y : gi.z + 2;

    const float* base = g_buf1 + b * 18 * 784;
    const float* p0 = base + ch0 * 784;
    const float* p1 = base + ch1 * 784;
    const float* p2 = base + ch2 * 784;

    float w0 = __ldg(w + g * 3 + 0);
    float w1 = __ldg(w + g * 3 + 1);
    float w2 = __ldg(w + g * 3 + 2);
    float bb = __ldg(bias + g);

    float m = 0.0f;
#pragma unroll
    for (int dy = 0; dy < 2; dy++) {
#pragma unroll
        for (int dx = 0; dx < 2; dx++) {
            int off = (2 * py + dy) * 28 + (2 * px + dx);
            float v = bb;
            v = fmaf(w0, p0[off], v);
            v = fmaf(w1, p1[off], v);
            v = fmaf(w2, p2[off], v);
            m = fmaxf(m, v);
        }
    }
    g_buf2[idx] = m;
}

// ---------------------------------------------------------------------------
// dw2: [64,51,14,14] -> [64,255,10,10]. Block=(b, 13-channel chunk),
// thread computes 10-wide x-strip with register row reuse.
// ---------------------------------------------------------------------------
__global__ void dw2_kernel(const float* __restrict__ w,
                           const float* __restrict__ bias) {
    __shared__ float s[13 * 200];
    int b = blockIdx.x >> 2, chunk = blockIdx.x & 3;
    int c0 = chunk * 13;
    int nch = (chunk == 3) ? 12 : 13;
    int tid = threadIdx.x;
    const float* src = g_buf2 + (b * 51 + c0) * 196;
    int n = nch * 196;
    for (int i = tid; i < n; i += 256)
        s[(i / 196) * 200 + i % 196] = src[i];
    __syncthreads();

    int nu = nch * 5 * 10;
    for (int u = tid; u < nu; u += 256) {
        int ol = u / 10, yo = u % 10;
        int o = c0 * 5 + ol;
        int cil = ol / 5;
        const float* wp = w + o * 25;
        float bb = __ldg(bias + o);
        float acc[10];
#pragma unroll
        for (int t = 0; t < 10; t++) acc[t] = bb;
        for (int ky = 0; ky < 5; ky++) {
            int rb = cil * 200 + (yo + ky) * 14;
            float r[14];
#pragma unroll
            for (int t = 0; t < 14; t++) r[t] = s[rb + t];
#pragma unroll
            for (int kx = 0; kx < 5; kx++) {
                float ww = __ldg(wp + ky * 5 + kx);
#pragma unroll
                for (int xo = 0; xo < 10; xo++)
                    acc[xo] = fmaf(r[xo + kx], ww, acc[xo]);
            }
        }
        float* dst = g_buf3 + (b * 255 + o) * 100 + yo * 10;
#pragma unroll
        for (int t = 0; t < 10; t++) dst[t] = acc[t];
    }
}

// ---------------------------------------------------------------------------
// pc2 + relu + pool, restructured:
//   out[g] = dot51(w[g], x[k-block]) + w[g,j]*(x[rep] - x[base+j])
// Thread = (quad of 4 same-k groups, pooled px) -> 16 accumulators.
// Block = (b, py, group-half). Weights (float4-padded) + input tile in smem.
// s_in layout: [260 rows][24]: top pair at +2px, bottom at +12+2px (zero-pad).
// s_w  layout: [slot][56] zero-padded (k-block dot runs 56 channels; extra
//              channels have w=0 and x rows are zeroed/real-finite).
// ---------------------------------------------------------------------------
__global__ void pc2pool_kernel(const float* __restrict__ w,
                               const float* __restrict__ bias) {
    extern __shared__ float sm[];
    float* s_in = sm;            // 260*24 = 6240 floats
    float* s_w = sm + 6240;      // up to 264*56 = 14784 floats
    int bid = blockIdx.x;
    int b = bid / 10;
    int t = bid % 10;
    int py = t >> 1, gh = t & 1;
    int q0 = gh * 66;
    int nq = gh ? 65 : 66;
    int tid = threadIdx.x;

    const float* src = g_buf3 + b * 25500 + (2 * py) * 10;
    for (int i = tid; i < 260 * 24; i += 256) {
        int ch = i / 24, off = i % 24, r = off / 12, col = off % 12;
        s_in[i] = (ch < 255 && col < 10) ? src[ch * 100 + r * 10 + col] : 0.f;
    }
    int nslots = nq * 4;
    for (int i = tid; i < nslots * 56; i += 256) {
        int sl = i / 56, c = i % 56;
        int g = g_g2sorted[q0 * 4 + sl].x;
        s_w[i] = (c < 51) ? __ldg(w + g * 51 + c) : 0.f;
    }
    __syncthreads();

    for (int u = tid; u < nq * 5; u += 256) {
        int ql = u / 5, px = u % 5;
        int slot0 = q0 * 4 + ql * 4;
        int base = g_g2sorted[slot0].w;
        float a[4][4];
#pragma unroll
        for (int s2 = 0; s2 < 4; s2++)
#pragma unroll
            for (int p = 0; p < 4; p++) a[s2][p] = 0.f;
        int wb = (ql * 4) * 56;
        int xb = base * 24 + 2 * px;
#pragma unroll 2
        for (int cc = 0; cc < 56; cc += 4) {
            float4 w0 = *(const float4*)&s_w[wb + cc];
            float4 w1 = *(const float4*)&s_w[wb + 56 + cc];
            float4 w2 = *(const float4*)&s_w[wb + 112 + cc];
            float4 w3 = *(const float4*)&s_w[wb + 168 + cc];
            float w0a[4] = {w0.x, w0.y, w0.z, w0.w};
            float w1a[4] = {w1.x, w1.y, w1.z, w1.w};
            float w2a[4] = {w2.x, w2.y, w2.z, w2.w};
            float w3a[4] = {w3.x, w3.y, w3.z, w3.w};
#pragma unroll
            for (int t2 = 0; t2 < 4; t2++) {
                float2 top = *(const float2*)&s_in[xb + (cc + t2) * 24];
                float2 bot = *(const float2*)&s_in[xb + (cc + t2) * 24 + 12];
                a[0][0] = fmaf(w0a[t2], top.x, a[0][0]);
                a[0][1] = fmaf(w0a[t2], top.y, a[0][1]);
                a[0][2] = fmaf(w0a[t2], bot.x, a[0][2]);
                a[0][3] = fmaf(w0a[t2], bot.y, a[0][3]);
                a[1][0] = fmaf(w1a[t2], top.x, a[1][0]);
                a[1][1] = fmaf(w1a[t2], top.y, a[1][1]);
                a[1][2] = fmaf(w1a[t2], bot.x, a[1][2]);
                a[1][3] = fmaf(w1a[t2], bot.y, a[1][3]);
                a[2][0] = fmaf(w2a[t2], top.x, a[2][0]);
                a[2][1] = fmaf(w2a[t2], top.y, a[2][1]);
                a[2][2] = fmaf(w2a[t2], bot.x, a[2][2]);
                a[2][3] = fmaf(w2a[t2], bot.y, a[2][3]);
                a[3][0] = fmaf(w3a[t2], top.x, a[3][0]);
                a[3][1] = fmaf(w3a[t2], top.y, a[3][1]);
                a[3][2] = fmaf(w3a[t2], bot.x, a[3][2]);
                a[3][3] = fmaf(w3a[t2], bot.y, a[3][3]);
            }
        }
        // permutation correction + bias + maxpool + relu, per slot
#pragma unroll
        for (int s2 = 0; s2 < 4; s2++) {
            int4 gi = g_g2sorted[slot0 + s2];
            float wj = s_w[wb + s2 * 56 + gi.y];
            int rb2 = gi.z * 24 + 2 * px;
            int bb2 = (base + gi.y) * 24 + 2 * px;
            float2 rt = *(const float2*)&s_in[rb2];
            float2 rb_ = *(const float2*)&s_in[rb2 + 12];
            float2 bt = *(const float2*)&s_in[bb2];
            float2 bb_ = *(const float2*)&s_in[bb2 + 12];
            float v0 = fmaf(wj, rt.x - bt.x, a[s2][0]);
            float v1 = fmaf(wj, rt.y - bt.y, a[s2][1]);
            float v2 = fmaf(wj, rb_.x - bb_.x, a[s2][2]);
            float v3 = fmaf(wj, rb_.y - bb_.y, a[s2][3]);
            float m = fmaxf(fmaxf(v0, v1), fmaxf(v2, v3)) + __ldg(bias + gi.x);
            g_buf4[(b * 515 + gi.x) * 25 + py * 5 + px] = fmaxf(m, 0.f);
        }
    }
}

// ---------------------------------------------------------------------------
// oo: 1x1 conv 515->100 (+relu), flattened output. Block=(b, oc-quarter),
// x + weight quarter in dynamic smem, thread tile = 2 oc x 2 pix.
// ---------------------------------------------------------------------------
__global__ void oo_kernel(const float* __restrict__ w,
                          const float* __restrict__ bias) {
    extern __shared__ float sm[];
    float* xs = sm;             // [516][26], zero-padded
    float* ws = sm + 13416;     // [26][520], zero-padded
    int b = blockIdx.x >> 2, qo = blockIdx.x & 3;
    int tid = threadIdx.x;

    const float* src = g_buf4 + b * 12875;
    for (int i = tid; i < 516 * 26; i += 256) {
        int c = i / 26, p = i % 26;
        xs[i] = (c < 515 && p < 25) ? src[c * 25 + p] : 0.f;
    }
    const float* wsrc = w + qo * 25 * 515;
    for (int i = tid; i < 26 * 520; i += 256) {
        int oc = i / 520, c = i % 520;
        ws[i] = (oc < 25 && c < 515) ? __ldg(wsrc + oc * 515 + c) : 0.f;
    }
    __syncthreads();

    if (tid < 169) {
        int ocp = tid / 13, pixp = tid % 13;
        int oc0 = 2 * ocp, pix0 = 2 * pixp;
        float a00 = 0.f, a01 = 0.f, a10 = 0.f, a11 = 0.f;
        const float* w0p = ws + oc0 * 520;
        const float* w1p = ws + (oc0 + 1) * 520;
        for (int cc = 0; cc < 516; cc += 4) {
            float4 w0 = *(const float4*)(w0p + cc);
            float4 w1 = *(const float4*)(w1p + cc);
            float w0a[4] = {w0.x, w0.y, w0.z, w0.w};
            float w1a[4] = {w1.x, w1.y, w1.z, w1.w};
#pragma unroll
            for (int t2 = 0; t2 < 4; t2++) {
                float2 xv = *(const float2*)&xs[(cc + t2) * 26 + pix0];
                a00 = fmaf(w0a[t2], xv.x, a00);
                a01 = fmaf(w0a[t2], xv.y, a01);
                a10 = fmaf(w1a[t2], xv.x, a10);
                a11 = fmaf(w1a[t2], xv.y, a11);
            }
        }
        int ocg0 = qo * 25 + oc0;
        float* dst = g_buf5 + b * 2500;
        float b0 = __ldg(bias + ocg0);
        dst[ocg0 * 25 + pix0] = fmaxf(a00 + b0, 0.f);
        if (pix0 + 1 < 25) dst[ocg0 * 25 + pix0 + 1] = fmaxf(a01 + b0, 0.f);
        if (oc0 + 1 < 25) {
            float b1 = __ldg(bias + ocg0 + 1);
            dst[(ocg0 + 1) * 25 + pix0] = fmaxf(a10 + b1, 0.f);
            if (pix0 + 1 < 25)
                dst[(ocg0 + 1) * 25 + pix0 + 1] = fmaxf(a11 + b1, 0.f);
        }
    }
}

// ---------------------------------------------------------------------------
// fc1: [64,2500] x [120,2500]^T + bias, relu. Warp tile = 4 outputs x 4 batch.
// ---------------------------------------------------------------------------
__global__ void fc1_kernel(const float* __restrict__ w,
                           const float* __restrict__ bias) {
    int wid = (blockIdx.x * blockDim.x + threadIdx.x) >> 5;
    int lane = threadIdx.x & 31;
    if (wid >= 480) return;          // 30 o-quads * 16 b-quads
    int o0 = (wid / 16) * 4;
    int b0 = (wid % 16) * 4;
    const float4* w4 = (const float4*)w;
    const float4* x4 = (const float4*)g_buf5;
    float a[16];
#pragma unroll
    for (int t = 0; t < 16; t++) a[t] = 0.f;
    for (int i = lane; i < 625; i += 32) {
        float4 wv[4], xv[4];
#pragma unroll
        for (int t = 0; t < 4; t++) wv[t] = __ldg(w4 + (o0 + t) * 625 + i);
#pragma unroll
        for (int t = 0; t < 4; t++) xv[t] = x4[(b0 + t) * 625 + i];
#pragma unroll
        for (int oi = 0; oi < 4; oi++)
#pragma unroll
            for (int bi = 0; bi < 4; bi++) {
                a[oi * 4 + bi] = fmaf(wv[oi].x, xv[bi].x, a[oi * 4 + bi]);
                a[oi * 4 + bi] = fmaf(wv[oi].y, xv[bi].y, a[oi * 4 + bi]);
                a[oi * 4 + bi] = fmaf(wv[oi].z, xv[bi].z, a[oi * 4 + bi]);
                a[oi * 4 + bi] = fmaf(wv[oi].w, xv[bi].w, a[oi * 4 + bi]);
            }
    }
#pragma unroll
    for (int off = 16; off; off >>= 1)
#pragma unroll
        for (int t = 0; t < 16; t++)
            a[t] += __shfl_xor_sync(0xffffffffu, a[t], off);
    if (lane < 16) {
        int oi = lane >> 2, bi = lane & 3;
        g_buf6[(b0 + bi) * 120 + o0 + oi] =
            fmaxf(a[lane] + __ldg(bias + o0 + oi), 0.f);
    }
}

// ---------------------------------------------------------------------------
// fc2 (relu) + fc3 fused. block per batch element.
// ---------------------------------------------------------------------------
__global__ void fc_tail_kernel(const float* __restrict__ w2,
                               const float* __restrict__ b2,
                               const float* __restrict__ w3,
                               const float* __restrict__ b3,
                               float* __restrict__ out) {
    __shared__ float h1[120];
    __shared__ float h2[84];
    int b = blockIdx.x;
    int t = threadIdx.x;
    if (t < 120) h1[t] = g_buf6[b * 120 + t];
    __syncthreads();
    if (t < 84) {
        float acc = __ldg(b2 + t);
        const float* wr = w2 + t * 120;
#pragma unroll 4
        for (int c = 0; c < 120; c++) acc = fmaf(__ldg(wr + c), h1[c], acc);
        h2[t] = fmaxf(acc, 0.0f);
    }
    __syncthreads();
    if (t < 10) {
        float acc = __ldg(b3 + t);
        const float* wr = w3 + t * 84;
#pragma unroll 4
        for (int c = 0; c < 84; c++) acc = fmaf(__ldg(wr + c), h2[c], acc);
        out[b * 10 + t] = acc;
    }
}

// ---------------------------------------------------------------------------
#define PC2_SMEM ((260 * 24 + 264 * 56) * (int)sizeof(float))   // 84096 B
#define OO_SMEM  ((516 * 26 + 26 * 520) * (int)sizeof(float))   // 107744 B

extern "C" void kernel_launch(void* const* d_in, const int* in_sizes, int n_in,
                              void* d_out, int out_size) {
    const float* x     = (const float*)d_in[0];
    const float* dw1_w = (const float*)d_in[1];
    const float* dw1_b = (const float*)d_in[2];
    const float* pc1_w = (const float*)d_in[3];
    const float* pc1_b = (const float*)d_in[4];
    const float* dw2_w = (const float*)d_in[5];
    const float* dw2_b = (const float*)d_in[6];
    const float* pc2_w = (const float*)d_in[7];
    const float* pc2_b = (const float*)d_in[8];
    const float* oo_w  = (const float*)d_in[9];
    const float* oo_b  = (const float*)d_in[10];
    const float* fc1_w = (const float*)d_in[11];
    const float* fc1_b = (const float*)d_in[12];
    const float* fc2_w = (const float*)d_in[13];
    const float* fc2_b = (const float*)d_in[14];
    const float* fc3_w = (const float*)d_in[15];
    const float* fc3_b = (const float*)d_in[16];
    float* out = (float*)d_out;

    static bool attr_set = false;
    if (!attr_set) {
        cudaFuncSetAttribute(pc2pool_kernel,
                             cudaFuncAttributeMaxDynamicSharedMemorySize,
                             PC2_SMEM);
        cudaFuncSetAttribute(oo_kernel,
                             cudaFuncAttributeMaxDynamicSharedMemorySize,
                             OO_SMEM);
        attr_set = true;
    }

    init_groupinfo_kernel<<<3, 256>>>();

    dw1_kernel<<<BATCH * 3, 256>>>(x, dw1_w, dw1_b);

    {
        int n = BATCH * 51 * 14 * 14;
        pc1pool_kernel<<<(n + 255) / 256, 256>>>(pc1_w, pc1_b);
    }

    dw2_kernel<<<BATCH * 4, 256>>>(dw2_w, dw2_b);

    pc2pool_kernel<<<BATCH * 10, 256, PC2_SMEM>>>(pc2_w, pc2_b);

    oo_kernel<<<BATCH * 4, 256, OO_SMEM>>>(oo_w, oo_b);

    fc1_kernel<<<60, 256>>>(fc1_w, fc1_b);

    fc_tail_kernel<<<BATCH, 128>>>(fc2_w, fc2_b, fc3_w, fc3_b, out);
}

// round 5
// speedup vs baseline: 2.5980x; 1.1692x over previous
#include <cuda_runtime.h>
#include <cuda_bf16.h>

// ---------------------------------------------------------------------------
// Net_80796924772492: small permuted-group CNN, B=64.
// front(dw1+pc1+relu+pool) -> dw2(5x5,g=51) -> pc2(+relu+pool)
//  -> 1x1 515->100 (+relu) -> fc1 -> fc2 -> fc3
// ---------------------------------------------------------------------------

#define BATCH 64

__device__ float g_buf2[BATCH * 51 * 14 * 14];   // front out
__device__ float g_buf3[BATCH * 255 * 10 * 10];  // dw2 out
__device__ float g_buf4[BATCH * 515 * 25];       // pc2+relu+pool out
__device__ float g_buf5[BATCH * 2500];           // oo out (flattened)
__device__ float g_buf6[BATCH * 120];            // fc1 out

// pc1 per-group info: (j, rep = i*ncpf+j, base = k*ncpf, 0)
__device__ int4 g_g1info[51];
// pc2 groups sorted by k, padded to quads of 4 (same k within a quad):
// slot -> (g, j, rep = i*51+j, base = k*51). 131 quads = 524 slots.
__device__ int4 g_g2sorted[524];

// ---------------------------------------------------------------------------
__device__ __forceinline__ int4 group_info(int g, int F, int ncpf) {
    int rem = g;
    int i = 0;
    for (;;) {
        int cnt = (F - i) + (ncpf - 1) * (F - 1 - i);
        if (rem < cnt) break;
        rem -= cnt;
        i++;
    }
    int j, k;
    if (rem < F - i) { j = 0; k = i + rem; }
    else {
        rem -= (F - i);
        j = 1 + rem / (F - 1 - i);
        k = i + 1 + rem % (F - 1 - i);
    }
    int4 r; r.x = j; r.y = i * ncpf + j; r.z = k * ncpf; r.w = 0;
    return r;
}

__global__ void init_groupinfo_kernel() {
    int t = blockIdx.x * blockDim.x + threadIdx.x;
    if (t < 51) {
        g_g1info[t] = group_info(t, 6, 3);
    } else if (t < 51 + 524) {
        int s = t - 51;
        const int qs[6] = {0, 1, 14, 40, 79, 131};
        const int Gk[5] = {1, 52, 103, 154, 205};
        int q = s >> 2;
        int k = 0;
        while (k < 4 && q >= qs[k + 1]) k++;
        int r = s - qs[k] * 4;
        if (r > Gk[k] - 1) r = Gk[k] - 1;   // pad: replicate last group
        int i, j;
        if (r <= k) { i = r; j = 0; }
        else { int r2 = r - (k + 1); i = r2 / 50; j = 1 + r2 % 50; }
        int base_i = 205 * i - 51 * (i * (i - 1) / 2);
        int off = (j == 0) ? (k - i)
                           : (5 - i) + (j - 1) * (4 - i) + (k - i - 1);
        int4 v; v.x = base_i + off; v.y = j; v.z = i * 51 + j; v.w = k * 51;
        g_g2sorted[s] = v;
    }
}

// ---------------------------------------------------------------------------
// front: dw1 (x[64,3,32,32] -> 18x28x28 in smem) + pc1(3-ch permuted 1x1)
//        + relu + 2x2 maxpool  ->  g_buf2 [64,51,14,14].
// Block = (b, vertical half h). Input rows r0..r0+17, output pooled rows
// h*7..h*7+6. dw1 result stays in shared memory.
// ---------------------------------------------------------------------------
__global__ void front_kernel(const float* __restrict__ x,
                             const float* __restrict__ dw1_w,
                             const float* __restrict__ dw1_b,
                             const float* __restrict__ pc1_w,
                             const float* __restrict__ pc1_b) {
    __shared__ float sx[3 * 594];    // [ch][18 rows][pitch 33]
    __shared__ float sd[18 * 396];   // [oc][14 rows][28]  (pitch 396)
    __shared__ float sw1[153];
    __shared__ float sb1[51];
    int b = blockIdx.x >> 1, h = blockIdx.x & 1;
    int r0 = h * 14;
    int tid = threadIdx.x;

    for (int i = tid; i < 3 * 576; i += 256) {
        int ch = i / 576, t = i % 576;
        int rr = t >> 5, c = t & 31;
        sx[ch * 594 + rr * 33 + c] = x[(b * 3 + ch) * 1024 + (r0 + rr) * 32 + c];
    }
    if (tid < 153) sw1[tid] = __ldg(pc1_w + tid);
    if (tid >= 160 && tid < 211) sb1[tid - 160] = __ldg(pc1_b + tid - 160);
    __syncthreads();

    // dw1: 18 oc x 14 local rows x 2 x-halves = 504 units (14-wide strips)
    for (int u = tid; u < 504; u += 256) {
        int xh = u & 1;
        int t = u >> 1;
        int yol = t % 14, oc = t / 14;
        int ci = oc / 6;
        const float* wp = dw1_w + oc * 25;
        float bb = __ldg(dw1_b + oc);
        float acc[14];
#pragma unroll
        for (int q = 0; q < 14; q++) acc[q] = bb;
        for (int ky = 0; ky < 5; ky++) {
            int rb = ci * 594 + (yol + ky) * 33 + xh * 14;
            float r[18];
#pragma unroll
            for (int q = 0; q < 18; q++) r[q] = sx[rb + q];
#pragma unroll
            for (int kx = 0; kx < 5; kx++) {
                float ww = __ldg(wp + ky * 5 + kx);
#pragma unroll
                for (int xo = 0; xo < 14; xo++)
                    acc[xo] = fmaf(r[xo + kx], ww, acc[xo]);
            }
        }
        float* dst = sd + oc * 396 + yol * 28 + xh * 14;
#pragma unroll
        for (int q = 0; q < 14; q++) dst[q] = acc[q];
    }
    __syncthreads();

    // pc1 + relu + pool: 51 g x 7 pooled rows x 14 px = 4998 units
    for (int u = tid; u < 4998; u += 256) {
        int px = u % 14;
        int t = u / 14;
        int pyl = t % 7, g = t / 7;
        int4 gi = g_g1info[g];
        int ch0 = (gi.x == 0) ? gi.y : gi.z + 0;
        int ch1 = (gi.x == 1) ? gi.y : gi.z + 1;
        int ch2 = (gi.x == 2) ? gi.y : gi.z + 2;
        const float* p0 = sd + ch0 * 396;
        const float* p1 = sd + ch1 * 396;
        const float* p2 = sd + ch2 * 396;
        float w0 = sw1[g * 3 + 0], w1 = sw1[g * 3 + 1], w2 = sw1[g * 3 + 2];
        float bb = sb1[g];
        float m = 0.0f;
#pragma unroll
        for (int dy = 0; dy < 2; dy++) {
#pragma unroll
            for (int dx = 0; dx < 2; dx++) {
                int off = (2 * pyl + dy) * 28 + 2 * px + dx;
                float v = bb;
                v = fmaf(w0, p0[off], v);
                v = fmaf(w1, p1[off], v);
                v = fmaf(w2, p2[off], v);
                m = fmaxf(m, v);
            }
        }
        g_buf2[((b * 51 + g) * 14 + h * 7 + pyl) * 14 + px] = m;
    }
}

// ---------------------------------------------------------------------------
// dw2: [64,51,14,14] -> [64,255,10,10]. Block = (b, 4-channel chunk) x 13,
// thread computes one 10-wide x-strip with register row reuse.
// ---------------------------------------------------------------------------
__global__ void dw2_kernel(const float* __restrict__ w,
                           const float* __restrict__ bias) {
    __shared__ float s[4 * 200];
    int b = blockIdx.x / 13, chunk = blockIdx.x % 13;
    int c0 = chunk * 4;
    int nch = (chunk == 12) ? 3 : 4;
    int tid = threadIdx.x;
    const float* src = g_buf2 + (b * 51 + c0) * 196;
    int n = nch * 196;
    for (int i = tid; i < n; i += 256)
        s[(i / 196) * 200 + i % 196] = src[i];
    __syncthreads();

    int nu = nch * 50;                 // (5 oc per in-ch) x 10 rows
    if (tid < nu) {
        int ol = tid / 10, yo = tid % 10;
        int o = c0 * 5 + ol;
        int cil = ol / 5;
        const float* wp = w + o * 25;
        float bb = __ldg(bias + o);
        float acc[10];
#pragma unroll
        for (int t = 0; t < 10; t++) acc[t] = bb;
        for (int ky = 0; ky < 5; ky++) {
            int rb = cil * 200 + (yo + ky) * 14;
            float r[14];
#pragma unroll
            for (int t = 0; t < 14; t++) r[t] = s[rb + t];
#pragma unroll
            for (int kx = 0; kx < 5; kx++) {
                float ww = __ldg(wp + ky * 5 + kx);
#pragma unroll
                for (int xo = 0; xo < 10; xo++)
                    acc[xo] = fmaf(r[xo + kx], ww, acc[xo]);
            }
        }
        float* dst = g_buf3 + (b * 255 + o) * 100 + yo * 10;
#pragma unroll
        for (int t = 0; t < 10; t++) dst[t] = acc[t];
    }
}

// ---------------------------------------------------------------------------
// pc2 + relu + pool:
//   out[g] = dot51(w[g], x[k-block]) + w[g,j]*(x[rep] - x[base+j])
// Thread = (quad of 4 same-k groups, pooled px) -> 16 accumulators, <=1/thread.
// Block = (b, py, group-third). grid = 64*5*3 = 960.
// ---------------------------------------------------------------------------
__global__ void pc2pool_kernel(const float* __restrict__ w,
                               const float* __restrict__ bias) {
    extern __shared__ float sm[];
    float* s_in = sm;            // 260*24 = 6240 floats
    float* s_w = sm + 6240;      // 44*4*56 = 9856 floats
    int bid = blockIdx.x;
    int b = bid / 15;
    int t = bid % 15;
    int py = t / 3, part = t % 3;
    int q0 = part * 44;
    int nq = (part == 2) ? 43 : 44;
    int tid = threadIdx.x;

    const float* src = g_buf3 + b * 25500 + (2 * py) * 10;
    for (int i = tid; i < 260 * 24; i += 256) {
        int ch = i / 24, off = i % 24, r = off / 12, col = off % 12;
        s_in[i] = (ch < 255 && col < 10) ? src[ch * 100 + r * 10 + col] : 0.f;
    }
    int nslots = nq * 4;
    for (int i = tid; i < nslots * 56; i += 256) {
        int sl = i / 56, c = i % 56;
        int g = g_g2sorted[(q0 + (sl >> 2)) * 4 + (sl & 3)].x;
        s_w[i] = (c < 51) ? __ldg(w + g * 51 + c) : 0.f;
    }
    __syncthreads();

    int u = tid;
    if (u < nq * 5) {
        int ql = u / 5, px = u % 5;
        int slot0 = (q0 + ql) * 4;
        int base = g_g2sorted[slot0].w;
        float a[4][4];
#pragma unroll
        for (int s2 = 0; s2 < 4; s2++)
#pragma unroll
            for (int p = 0; p < 4; p++) a[s2][p] = 0.f;
        int wb = (ql * 4) * 56;
        int xb = base * 24 + 2 * px;
#pragma unroll 2
        for (int cc = 0; cc < 56; cc += 4) {
            float4 w0 = *(const float4*)&s_w[wb + cc];
            float4 w1 = *(const float4*)&s_w[wb + 56 + cc];
            float4 w2 = *(const float4*)&s_w[wb + 112 + cc];
            float4 w3 = *(const float4*)&s_w[wb + 168 + cc];
            float w0a[4] = {w0.x, w0.y, w0.z, w0.w};
            float w1a[4] = {w1.x, w1.y, w1.z, w1.w};
            float w2a[4] = {w2.x, w2.y, w2.z, w2.w};
            float w3a[4] = {w3.x, w3.y, w3.z, w3.w};
#pragma unroll
            for (int t2 = 0; t2 < 4; t2++) {
                float2 top = *(const float2*)&s_in[xb + (cc + t2) * 24];
                float2 bot = *(const float2*)&s_in[xb + (cc + t2) * 24 + 12];
                a[0][0] = fmaf(w0a[t2], top.x, a[0][0]);
                a[0][1] = fmaf(w0a[t2], top.y, a[0][1]);
                a[0][2] = fmaf(w0a[t2], bot.x, a[0][2]);
                a[0][3] = fmaf(w0a[t2], bot.y, a[0][3]);
                a[1][0] = fmaf(w1a[t2], top.x, a[1][0]);
                a[1][1] = fmaf(w1a[t2], top.y, a[1][1]);
                a[1][2] = fmaf(w1a[t2], bot.x, a[1][2]);
                a[1][3] = fmaf(w1a[t2], bot.y, a[1][3]);
                a[2][0] = fmaf(w2a[t2], top.x, a[2][0]);
                a[2][1] = fmaf(w2a[t2], top.y, a[2][1]);
                a[2][2] = fmaf(w2a[t2], bot.x, a[2][2]);
                a[2][3] = fmaf(w2a[t2], bot.y, a[2][3]);
                a[3][0] = fmaf(w3a[t2], top.x, a[3][0]);
                a[3][1] = fmaf(w3a[t2], top.y, a[3][1]);
                a[3][2] = fmaf(w3a[t2], bot.x, a[3][2]);
                a[3][3] = fmaf(w3a[t2], bot.y, a[3][3]);
            }
        }
#pragma unroll
        for (int s2 = 0; s2 < 4; s2++) {
            int4 gi = g_g2sorted[slot0 + s2];
            float wj = s_w[wb + s2 * 56 + gi.y];
            int rb2 = gi.z * 24 + 2 * px;
            int bb2 = (base + gi.y) * 24 + 2 * px;
            float2 rt = *(const float2*)&s_in[rb2];
            float2 rb_ = *(const float2*)&s_in[rb2 + 12];
            float2 bt = *(const float2*)&s_in[bb2];
            float2 bb_ = *(const float2*)&s_in[bb2 + 12];
            float v0 = fmaf(wj, rt.x - bt.x, a[s2][0]);
            float v1 = fmaf(wj, rt.y - bt.y, a[s2][1]);
            float v2 = fmaf(wj, rb_.x - bb_.x, a[s2][2]);
            float v3 = fmaf(wj, rb_.y - bb_.y, a[s2][3]);
            float m = fmaxf(fmaxf(v0, v1), fmaxf(v2, v3)) + __ldg(bias + gi.x);
            g_buf4[(b * 515 + gi.x) * 25 + py * 5 + px] = fmaxf(m, 0.f);
        }
    }
}

// ---------------------------------------------------------------------------
// oo: 1x1 conv 515->100 (+relu), flattened output. Block=(b, oc-quarter),
// x + weight quarter in dynamic smem, thread tile = 2 oc x 2 pix.
// ---------------------------------------------------------------------------
__global__ void oo_kernel(const float* __restrict__ w,
                          const float* __restrict__ bias) {
    extern __shared__ float sm[];
    float* xs = sm;             // [516][26], zero-padded
    float* ws = sm + 13416;     // [26][520], zero-padded
    int b = blockIdx.x >> 2, qo = blockIdx.x & 3;
    int tid = threadIdx.x;

    const float* src = g_buf4 + b * 12875;
    for (int i = tid; i < 516 * 26; i += 192) {
        int c = i / 26, p = i % 26;
        xs[i] = (c < 515 && p < 25) ? src[c * 25 + p] : 0.f;
    }
    const float* wsrc = w + qo * 25 * 515;
    for (int i = tid; i < 26 * 520; i += 192) {
        int oc = i / 520, c = i % 520;
        ws[i] = (oc < 25 && c < 515) ? __ldg(wsrc + oc * 515 + c) : 0.f;
    }
    __syncthreads();

    if (tid < 169) {
        int ocp = tid / 13, pixp = tid % 13;
        int oc0 = 2 * ocp, pix0 = 2 * pixp;
        float a00 = 0.f, a01 = 0.f, a10 = 0.f, a11 = 0.f;
        const float* w0p = ws + oc0 * 520;
        const float* w1p = ws + (oc0 + 1) * 520;
        for (int cc = 0; cc < 516; cc += 4) {
            float4 w0 = *(const float4*)(w0p + cc);
            float4 w1 = *(const float4*)(w1p + cc);
            float w0a[4] = {w0.x, w0.y, w0.z, w0.w};
            float w1a[4] = {w1.x, w1.y, w1.z, w1.w};
#pragma unroll
            for (int t2 = 0; t2 < 4; t2++) {
                float2 xv = *(const float2*)&xs[(cc + t2) * 26 + pix0];
                a00 = fmaf(w0a[t2], xv.x, a00);
                a01 = fmaf(w0a[t2], xv.y, a01);
                a10 = fmaf(w1a[t2], xv.x, a10);
                a11 = fmaf(w1a[t2], xv.y, a11);
            }
        }
        int ocg0 = qo * 25 + oc0;
        float* dst = g_buf5 + b * 2500;
        float b0 = __ldg(bias + ocg0);
        dst[ocg0 * 25 + pix0] = fmaxf(a00 + b0, 0.f);
        if (pix0 + 1 < 25) dst[ocg0 * 25 + pix0 + 1] = fmaxf(a01 + b0, 0.f);
        if (oc0 + 1 < 25) {
            float b1 = __ldg(bias + ocg0 + 1);
            dst[(ocg0 + 1) * 25 + pix0] = fmaxf(a10 + b1, 0.f);
            if (pix0 + 1 < 25)
                dst[(ocg0 + 1) * 25 + pix0 + 1] = fmaxf(a11 + b1, 0.f);
        }
    }
}

// ---------------------------------------------------------------------------
// fc1: [64,2500] x [120,2500]^T + bias, relu. Warp tile = 4 outputs x 4 batch.
// ---------------------------------------------------------------------------
__global__ void fc1_kernel(const float* __restrict__ w,
                           const float* __restrict__ bias) {
    int wid = (blockIdx.x * blockDim.x + threadIdx.x) >> 5;
    int lane = threadIdx.x & 31;
    if (wid >= 480) return;          // 30 o-quads * 16 b-quads
    int o0 = (wid / 16) * 4;
    int b0 = (wid % 16) * 4;
    const float4* w4 = (const float4*)w;
    const float4* x4 = (const float4*)g_buf5;
    float a[16];
#pragma unroll
    for (int t = 0; t < 16; t++) a[t] = 0.f;
    for (int i = lane; i < 625; i += 32) {
        float4 wv[4], xv[4];
#pragma unroll
        for (int t = 0; t < 4; t++) wv[t] = __ldg(w4 + (o0 + t) * 625 + i);
#pragma unroll
        for (int t = 0; t < 4; t++) xv[t] = x4[(b0 + t) * 625 + i];
#pragma unroll
        for (int oi = 0; oi < 4; oi++)
#pragma unroll
            for (int bi = 0; bi < 4; bi++) {
                a[oi * 4 + bi] = fmaf(wv[oi].x, xv[bi].x, a[oi * 4 + bi]);
                a[oi * 4 + bi] = fmaf(wv[oi].y, xv[bi].y, a[oi * 4 + bi]);
                a[oi * 4 + bi] = fmaf(wv[oi].z, xv[bi].z, a[oi * 4 + bi]);
                a[oi * 4 + bi] = fmaf(wv[oi].w, xv[bi].w, a[oi * 4 + bi]);
            }
    }
#pragma unroll
    for (int off = 16; off; off >>= 1)
#pragma unroll
        for (int t = 0; t < 16; t++)
            a[t] += __shfl_xor_sync(0xffffffffu, a[t], off);
    if (lane < 16) {
        int oi = lane >> 2, bi = lane & 3;
        g_buf6[(b0 + bi) * 120 + o0 + oi] =
            fmaxf(a[lane] + __ldg(bias + o0 + oi), 0.f);
    }
}

// ---------------------------------------------------------------------------
// fc2 (relu) + fc3 fused. block per batch element.
// ---------------------------------------------------------------------------
__global__ void fc_tail_kernel(const float* __restrict__ w2,
                               const float* __restrict__ b2,
                               const float* __restrict__ w3,
                               const float* __restrict__ b3,
                               float* __restrict__ out) {
    __shared__ float h1[120];
    __shared__ float h2[84];
    int b = blockIdx.x;
    int t = threadIdx.x;
    if (t < 120) h1[t] = g_buf6[b * 120 + t];
    __syncthreads();
    if (t < 84) {
        float acc = __ldg(b2 + t);
        const float* wr = w2 + t * 120;
#pragma unroll 4
        for (int c = 0; c < 120; c++) acc = fmaf(__ldg(wr + c), h1[c], acc);
        h2[t] = fmaxf(acc, 0.0f);
    }
    __syncthreads();
    if (t < 10) {
        float acc = __ldg(b3 + t);
        const float* wr = w3 + t * 84;
#pragma unroll 4
        for (int c = 0; c < 84; c++) acc = fmaf(__ldg(wr + c), h2[c], acc);
        out[b * 10 + t] = acc;
    }
}

// ---------------------------------------------------------------------------
#define PC2_SMEM ((6240 + 44 * 4 * 56) * (int)sizeof(float))    // 64384 B
#define OO_SMEM  ((516 * 26 + 26 * 520) * (int)sizeof(float))   // 107744 B

extern "C" void kernel_launch(void* const* d_in, const int* in_sizes, int n_in,
                              void* d_out, int out_size) {
    const float* x     = (const float*)d_in[0];
    const float* dw1_w = (const float*)d_in[1];
    const float* dw1_b = (const float*)d_in[2];
    const float* pc1_w = (const float*)d_in[3];
    const float* pc1_b = (const float*)d_in[4];
    const float* dw2_w = (const float*)d_in[5];
    const float* dw2_b = (const float*)d_in[6];
    const float* pc2_w = (const float*)d_in[7];
    const float* pc2_b = (const float*)d_in[8];
    const float* oo_w  = (const float*)d_in[9];
    const float* oo_b  = (const float*)d_in[10];
    const float* fc1_w = (const float*)d_in[11];
    const float* fc1_b = (const float*)d_in[12];
    const float* fc2_w = (const float*)d_in[13];
    const float* fc2_b = (const float*)d_in[14];
    const float* fc3_w = (const float*)d_in[15];
    const float* fc3_b = (const float*)d_in[16];
    float* out = (float*)d_out;

    static bool attr_set = false;
    if (!attr_set) {
        cudaFuncSetAttribute(pc2pool_kernel,
                             cudaFuncAttributeMaxDynamicSharedMemorySize,
                             PC2_SMEM);
        cudaFuncSetAttribute(oo_kernel,
                             cudaFuncAttributeMaxDynamicSharedMemorySize,
                             OO_SMEM);
        attr_set = true;
    }

    init_groupinfo_kernel<<<3, 256>>>();

    front_kernel<<<BATCH * 2, 256>>>(x, dw1_w, dw1_b, pc1_w, pc1_b);

    dw2_kernel<<<BATCH * 13, 256>>>(dw2_w, dw2_b);

    pc2pool_kernel<<<BATCH * 15, 256, PC2_SMEM>>>(pc2_w, pc2_b);

    oo_kernel<<<BATCH * 4, 192, OO_SMEM>>>(oo_w, oo_b);

    fc1_kernel<<<60, 256>>>(fc1_w, fc1_b);

    fc_tail_kernel<<<BATCH, 128>>>(fc2_w, fc2_b, fc3_w, fc3_b, out);
}

// round 6
// speedup vs baseline: 2.7866x; 1.0726x over previous
#include <cuda_runtime.h>
#include <cuda_bf16.h>

// ---------------------------------------------------------------------------
// Net_80796924772492: small permuted-group CNN, B=64.
// front(dw1+pc1+relu+pool) -> dw2(5x5,g=51, writes padded pc2 layout)
//  -> pc2(+relu+pool, padded oo layout) -> oo 1x1 515->100 (+relu)
//  -> fc1 -> fc2 -> fc3
// ---------------------------------------------------------------------------

#define BATCH 64

__device__ float g_buf2[BATCH * 51 * 14 * 14];   // front out
__device__ float g_buf3p[BATCH * 31200];         // dw2 out, [b][py5][260ch][24]
__device__ float g_buf4[BATCH * 516 * 26];       // pc2 out, padded [516][26]
__device__ float g_buf5[BATCH * 2500];           // oo out (flattened)
__device__ float g_buf6[BATCH * 120];            // fc1 out

// pc1 per-group info: (j, rep = i*ncpf+j, base = k*ncpf, 0)
__device__ int4 g_g1info[51];
// pc2 groups sorted by k, padded to quads of 4 (same k within a quad):
// slot -> (g, j, rep = i*51+j, base = k*51). 131 quads = 524 slots.
__device__ int4 g_g2sorted[524];
// pre-padded pc2 weights: [slot 524][56] (zero pad c>=51 and dup slots)
__device__ float g_w2pad[524 * 56];
// pre-padded oo weights: [104 oc][520] zero-padded
__device__ float g_oow_pad[104 * 520];

// ---------------------------------------------------------------------------
__device__ __forceinline__ int4 group_info1(int g) {   // F=6, ncpf=3
    int rem = g, i = 0;
    for (;;) {
        int cnt = (6 - i) + 2 * (5 - i);
        if (rem < cnt) break;
        rem -= cnt; i++;
    }
    int j, k;
    if (rem < 6 - i) { j = 0; k = i + rem; }
    else { rem -= (6 - i); j = 1 + rem / (5 - i); k = i + 1 + rem % (5 - i); }
    int4 r; r.x = j; r.y = i * 3 + j; r.z = k * 3; r.w = 0;
    return r;
}

// pc2 slot decode (pure function of slot index s in [0,524))
__device__ __forceinline__ int4 slot_info2(int s) {
    const int qs[6] = {0, 1, 14, 40, 79, 131};
    const int Gk[5] = {1, 52, 103, 154, 205};
    int q = s >> 2;
    int k = 0;
    while (k < 4 && q >= qs[k + 1]) k++;
    int r = s - qs[k] * 4;
    if (r > Gk[k] - 1) r = Gk[k] - 1;       // pad: replicate last group
    int i, j;
    if (r <= k) { i = r; j = 0; }
    else { int r2 = r - (k + 1); i = r2 / 50; j = 1 + r2 % 50; }
    int base_i = 205 * i - 51 * (i * (i - 1) / 2);
    int off = (j == 0) ? (k - i) : (5 - i) + (j - 1) * (4 - i) + (k - i - 1);
    int4 v; v.x = base_i + off; v.y = j; v.z = i * 51 + j; v.w = k * 51;
    return v;
}

// ---------------------------------------------------------------------------
// init: group tables + pre-padded weight layouts + g_buf4 pad zeros.
// Work regions (grid-stride):
//  A [0,51): g1info          B [51,575): g2sorted
//  C [575,575+29344): w2pad  D: oow_pad 54080   E: g_buf4 pads 64*541
// ---------------------------------------------------------------------------
__global__ void init_kernel(const float* __restrict__ pc2_w,
                            const float* __restrict__ oo_w) {
    const int CA = 51, CB = 524, CC = 524 * 56, CD = 104 * 520, CE = 64 * 541;
    int total = CA + CB + CC + CD + CE;
    for (int t = blockIdx.x * blockDim.x + threadIdx.x; t < total;
         t += gridDim.x * blockDim.x) {
        int i = t;
        if (i < CA) { g_g1info[i] = group_info1(i); continue; }
        i -= CA;
        if (i < CB) { g_g2sorted[i] = slot_info2(i); continue; }
        i -= CB;
        if (i < CC) {
            int s = i / 56, c = i % 56;
            int g = slot_info2(s).x;
            g_w2pad[i] = (c < 51) ? __ldg(pc2_w + g * 51 + c) : 0.f;
            continue;
        }
        i -= CC;
        if (i < CD) {
            int r = i / 520, c = i % 520;
            g_oow_pad[i] = (r < 100 && c < 515) ? __ldg(oo_w + r * 515 + c) : 0.f;
            continue;
        }
        i -= CD;
        {
            int b = i / 541, r = i % 541;
            if (r < 515) g_buf4[b * 13416 + r * 26 + 25] = 0.f;
            else g_buf4[b * 13416 + 515 * 26 + (r - 515)] = 0.f;
        }
    }
}

// ---------------------------------------------------------------------------
// front: dw1 (x[64,3,32,32] -> 18x28x28 in smem) + pc1(3-ch permuted 1x1)
//        + relu + 2x2 maxpool  ->  g_buf2 [64,51,14,14].
// Block = (b, vertical half h).
// ---------------------------------------------------------------------------
__global__ void front_kernel(const float* __restrict__ x,
                             const float* __restrict__ dw1_w,
                             const float* __restrict__ dw1_b,
                             const float* __restrict__ pc1_w,
                             const float* __restrict__ pc1_b) {
    __shared__ float sx[3 * 594];    // [ch][18 rows][pitch 33]
    __shared__ float sd[18 * 396];   // [oc][14 rows][28]
    __shared__ float sw1[153];
    __shared__ float sb1[51];
    int b = blockIdx.x >> 1, h = blockIdx.x & 1;
    int r0 = h * 14;
    int tid = threadIdx.x;

    for (int i = tid; i < 3 * 576; i += 256) {
        int ch = i / 576, t = i % 576;
        int rr = t >> 5, c = t & 31;
        sx[ch * 594 + rr * 33 + c] = x[(b * 3 + ch) * 1024 + (r0 + rr) * 32 + c];
    }
    if (tid < 153) sw1[tid] = __ldg(pc1_w + tid);
    if (tid >= 160 && tid < 211) sb1[tid - 160] = __ldg(pc1_b + tid - 160);
    __syncthreads();

    for (int u = tid; u < 504; u += 256) {   // 18 oc x 14 rows x 2 halves
        int xh = u & 1;
        int t = u >> 1;
        int yol = t % 14, oc = t / 14;
        int ci = oc / 6;
        const float* wp = dw1_w + oc * 25;
        float bb = __ldg(dw1_b + oc);
        float acc[14];
#pragma unroll
        for (int q = 0; q < 14; q++) acc[q] = bb;
        for (int ky = 0; ky < 5; ky++) {
            int rb = ci * 594 + (yol + ky) * 33 + xh * 14;
            float r[18];
#pragma unroll
            for (int q = 0; q < 18; q++) r[q] = sx[rb + q];
#pragma unroll
            for (int kx = 0; kx < 5; kx++) {
                float ww = __ldg(wp + ky * 5 + kx);
#pragma unroll
                for (int xo = 0; xo < 14; xo++)
                    acc[xo] = fmaf(r[xo + kx], ww, acc[xo]);
            }
        }
        float* dst = sd + oc * 396 + yol * 28 + xh * 14;
#pragma unroll
        for (int q = 0; q < 14; q++) dst[q] = acc[q];
    }
    __syncthreads();

    for (int u = tid; u < 4998; u += 256) {  // 51 g x 7 prow x 14 px
        int px = u % 14;
        int t = u / 14;
        int pyl = t % 7, g = t / 7;
        int4 gi = g_g1info[g];
        int ch0 = (gi.x == 0) ? gi.y : gi.z + 0;
        int ch1 = (gi.x == 1) ? gi.y : gi.z + 1;
        int ch2 = (gi.x == 2) ? gi.y : gi.z + 2;
        const float* p0 = sd + ch0 * 396;
        const float* p1 = sd + ch1 * 396;
        const float* p2 = sd + ch2 * 396;
        float w0 = sw1[g * 3 + 0], w1 = sw1[g * 3 + 1], w2 = sw1[g * 3 + 2];
        float bb = sb1[g];
        float m = 0.0f;
#pragma unroll
        for (int dy = 0; dy < 2; dy++) {
#pragma unroll
            for (int dx = 0; dx < 2; dx++) {
                int off = (2 * pyl + dy) * 28 + 2 * px + dx;
                float v = bb;
                v = fmaf(w0, p0[off], v);
                v = fmaf(w1, p1[off], v);
                v = fmaf(w2, p2[off], v);
                m = fmaxf(m, v);
            }
        }
        g_buf2[((b * 51 + g) * 14 + h * 7 + pyl) * 14 + px] = m;
    }
}

// ---------------------------------------------------------------------------
// dw2: [64,51,14,14] -> padded [b][py][260ch][24]. Block=(b, 4-ch chunk)x13.
// Also zeroes pad channels 255..259 (chunk 12's spare threads).
// ---------------------------------------------------------------------------
__global__ void dw2_kernel(const float* __restrict__ w,
                           const float* __restrict__ bias) {
    __shared__ float s[4 * 200];
    int b = blockIdx.x / 13, chunk = blockIdx.x % 13;
    int c0 = chunk * 4;
    int nch = (chunk == 12) ? 3 : 4;
    int tid = threadIdx.x;
    const float* src = g_buf2 + (b * 51 + c0) * 196;
    int n = nch * 196;
    for (int i = tid; i < n; i += 256)
        s[(i / 196) * 200 + i % 196] = src[i];
    __syncthreads();

    int nu = nch * 50;
    if (tid < nu) {
        int ol = tid / 10, yo = tid % 10;
        int o = c0 * 5 + ol;
        int cil = ol / 5;
        const float* wp = w + o * 25;
        float bb = __ldg(bias + o);
        float acc[10];
#pragma unroll
        for (int t = 0; t < 10; t++) acc[t] = bb;
        for (int ky = 0; ky < 5; ky++) {
            int rb = cil * 200 + (yo + ky) * 14;
            float r[14];
#pragma unroll
            for (int t = 0; t < 14; t++) r[t] = s[rb + t];
#pragma unroll
            for (int kx = 0; kx < 5; kx++) {
                float ww = __ldg(wp + ky * 5 + kx);
#pragma unroll
                for (int xo = 0; xo < 10; xo++)
                    acc[xo] = fmaf(r[xo + kx], ww, acc[xo]);
            }
        }
        float* dst = g_buf3p + b * 31200 + (yo >> 1) * 6240 + o * 24 +
                     (yo & 1) * 12;
#pragma unroll
        for (int t = 0; t < 10; t++) dst[t] = acc[t];
        dst[10] = 0.f;
        dst[11] = 0.f;
    }
    if (chunk == 12 && tid >= 150) {
        for (int i = tid - 150; i < 600; i += 106) {
            int py = i / 120, r = i % 120;
            g_buf3p[b * 31200 + py * 6240 + 6120 + r] = 0.f;
        }
    }
}

// ---------------------------------------------------------------------------
// pc2 + relu + pool:
//   out[g] = dot51(w[g], x[k-block]) + w[g,j]*(x[rep] - x[base+j])
// Thread = (quad of 4 same-k groups, pooled px). Block = (b, py, third).
// All staging is contiguous float4 from pre-padded layouts.
// ---------------------------------------------------------------------------
__global__ void pc2pool_kernel(const float* __restrict__ bias) {
    extern __shared__ float sm[];
    float* s_in = sm;            // 6240 floats
    float* s_w = sm + 6240;      // up to 44*224 = 9856 floats
    int bid = blockIdx.x;
    int b = bid / 15;
    int t = bid % 15;
    int py = t / 3, part = t % 3;
    int q0 = part * 44;
    int nq = (part == 2) ? 43 : 44;
    int tid = threadIdx.x;

    {
        float4* si4 = (float4*)s_in;
        const float4* g4 = (const float4*)(g_buf3p + b * 31200 + py * 6240);
        for (int i = tid; i < 1560; i += 256) si4[i] = g4[i];
        float4* sw4 = (float4*)s_w;
        const float4* w4 = (const float4*)(g_w2pad + q0 * 224);
        int nf4 = nq * 56;
        for (int i = tid; i < nf4; i += 256) sw4[i] = w4[i];
    }
    __syncthreads();

    int u = tid;
    if (u < nq * 5) {
        int ql = u / 5, px = u % 5;
        int slot0 = (q0 + ql) * 4;
        int base = g_g2sorted[slot0].w;
        float a[4][4];
#pragma unroll
        for (int s2 = 0; s2 < 4; s2++)
#pragma unroll
            for (int p = 0; p < 4; p++) a[s2][p] = 0.f;
        int wb = ql * 224;
        int xb = base * 24 + 2 * px;
#pragma unroll 2
        for (int cc = 0; cc < 56; cc += 4) {
            float4 w0 = *(const float4*)&s_w[wb + cc];
            float4 w1 = *(const float4*)&s_w[wb + 56 + cc];
            float4 w2 = *(const float4*)&s_w[wb + 112 + cc];
            float4 w3 = *(const float4*)&s_w[wb + 168 + cc];
            float w0a[4] = {w0.x, w0.y, w0.z, w0.w};
            float w1a[4] = {w1.x, w1.y, w1.z, w1.w};
            float w2a[4] = {w2.x, w2.y, w2.z, w2.w};
            float w3a[4] = {w3.x, w3.y, w3.z, w3.w};
#pragma unroll
            for (int t2 = 0; t2 < 4; t2++) {
                float2 top = *(const float2*)&s_in[xb + (cc + t2) * 24];
                float2 bot = *(const float2*)&s_in[xb + (cc + t2) * 24 + 12];
                a[0][0] = fmaf(w0a[t2], top.x, a[0][0]);
                a[0][1] = fmaf(w0a[t2], top.y, a[0][1]);
                a[0][2] = fmaf(w0a[t2], bot.x, a[0][2]);
                a[0][3] = fmaf(w0a[t2], bot.y, a[0][3]);
                a[1][0] = fmaf(w1a[t2], top.x, a[1][0]);
                a[1][1] = fmaf(w1a[t2], top.y, a[1][1]);
                a[1][2] = fmaf(w1a[t2], bot.x, a[1][2]);
                a[1][3] = fmaf(w1a[t2], bot.y, a[1][3]);
                a[2][0] = fmaf(w2a[t2], top.x, a[2][0]);
                a[2][1] = fmaf(w2a[t2], top.y, a[2][1]);
                a[2][2] = fmaf(w2a[t2], bot.x, a[2][2]);
                a[2][3] = fmaf(w2a[t2], bot.y, a[2][3]);
                a[3][0] = fmaf(w3a[t2], top.x, a[3][0]);
                a[3][1] = fmaf(w3a[t2], top.y, a[3][1]);
                a[3][2] = fmaf(w3a[t2], bot.x, a[3][2]);
                a[3][3] = fmaf(w3a[t2], bot.y, a[3][3]);
            }
        }
#pragma unroll
        for (int s2 = 0; s2 < 4; s2++) {
            int4 gi = g_g2sorted[slot0 + s2];
            float wj = s_w[wb + s2 * 56 + gi.y];
            int rb2 = gi.z * 24 + 2 * px;
            int bb2 = (base + gi.y) * 24 + 2 * px;
            float2 rt = *(const float2*)&s_in[rb2];
            float2 rb_ = *(const float2*)&s_in[rb2 + 12];
            float2 bt = *(const float2*)&s_in[bb2];
            float2 bb_ = *(const float2*)&s_in[bb2 + 12];
            float v0 = fmaf(wj, rt.x - bt.x, a[s2][0]);
            float v1 = fmaf(wj, rt.y - bt.y, a[s2][1]);
            float v2 = fmaf(wj, rb_.x - bb_.x, a[s2][2]);
            float v3 = fmaf(wj, rb_.y - bb_.y, a[s2][3]);
            float m = fmaxf(fmaxf(v0, v1), fmaxf(v2, v3)) + __ldg(bias + gi.x);
            g_buf4[b * 13416 + gi.x * 26 + py * 5 + px] = fmaxf(m, 0.f);
        }
    }
}

// ---------------------------------------------------------------------------
// oo: 1x1 conv 515->100 (+relu), flattened. Block=(b, oc-quarter).
// Staging: contiguous float4 from padded layouts.
// ---------------------------------------------------------------------------
__global__ void oo_kernel(const float* __restrict__ bias) {
    extern __shared__ float sm[];
    float* xs = sm;             // [516][26]
    float* ws = sm + 13416;     // [26][520]
    int b = blockIdx.x >> 2, qo = blockIdx.x & 3;
    int tid = threadIdx.x;

    {
        float4* xs4 = (float4*)xs;
        const float4* s4 = (const float4*)(g_buf4 + b * 13416);
        for (int i = tid; i < 3354; i += 192) xs4[i] = s4[i];
        float4* ws4 = (float4*)ws;
        const float4* w4 = (const float4*)(g_oow_pad + qo * 13000);
        for (int i = tid; i < 3380; i += 192) ws4[i] = w4[i];
    }
    __syncthreads();

    if (tid < 169) {
        int ocp = tid / 13, pixp = tid % 13;
        int oc0 = 2 * ocp, pix0 = 2 * pixp;
        float a00 = 0.f, a01 = 0.f, a10 = 0.f, a11 = 0.f;
        const float* w0p = ws + oc0 * 520;
        const float* w1p = ws + (oc0 + 1) * 520;
        for (int cc = 0; cc < 516; cc += 4) {
            float4 w0 = *(const float4*)(w0p + cc);
            float4 w1 = *(const float4*)(w1p + cc);
            float w0a[4] = {w0.x, w0.y, w0.z, w0.w};
            float w1a[4] = {w1.x, w1.y, w1.z, w1.w};
#pragma unroll
            for (int t2 = 0; t2 < 4; t2++) {
                float2 xv = *(const float2*)&xs[(cc + t2) * 26 + pix0];
                a00 = fmaf(w0a[t2], xv.x, a00);
                a01 = fmaf(w0a[t2], xv.y, a01);
                a10 = fmaf(w1a[t2], xv.x, a10);
                a11 = fmaf(w1a[t2], xv.y, a11);
            }
        }
        int ocg0 = qo * 25 + oc0;
        float* dst = g_buf5 + b * 2500;
        float b0 = __ldg(bias + ocg0);
        dst[ocg0 * 25 + pix0] = fmaxf(a00 + b0, 0.f);
        if (pix0 + 1 < 25) dst[ocg0 * 25 + pix0 + 1] = fmaxf(a01 + b0, 0.f);
        if (oc0 + 1 < 25) {
            float b1 = __ldg(bias + ocg0 + 1);
            dst[(ocg0 + 1) * 25 + pix0] = fmaxf(a10 + b1, 0.f);
            if (pix0 + 1 < 25)
                dst[(ocg0 + 1) * 25 + pix0 + 1] = fmaxf(a11 + b1, 0.f);
        }
    }
}

// ---------------------------------------------------------------------------
// fc1: [64,2500] x [120,2500]^T + bias, relu. Warp tile = 4 outputs x 4 batch.
// ---------------------------------------------------------------------------
__global__ void fc1_kernel(const float* __restrict__ w,
                           const float* __restrict__ bias) {
    int wid = (blockIdx.x * blockDim.x + threadIdx.x) >> 5;
    int lane = threadIdx.x & 31;
    if (wid >= 480) return;
    int o0 = (wid / 16) * 4;
    int b0 = (wid % 16) * 4;
    const float4* w4 = (const float4*)w;
    const float4* x4 = (const float4*)g_buf5;
    float a[16];
#pragma unroll
    for (int t = 0; t < 16; t++) a[t] = 0.f;
    for (int i = lane; i < 625; i += 32) {
        float4 wv[4], xv[4];
#pragma unroll
        for (int t = 0; t < 4; t++) wv[t] = __ldg(w4 + (o0 + t) * 625 + i);
#pragma unroll
        for (int t = 0; t < 4; t++) xv[t] = x4[(b0 + t) * 625 + i];
#pragma unroll
        for (int oi = 0; oi < 4; oi++)
#pragma unroll
            for (int bi = 0; bi < 4; bi++) {
                a[oi * 4 + bi] = fmaf(wv[oi].x, xv[bi].x, a[oi * 4 + bi]);
                a[oi * 4 + bi] = fmaf(wv[oi].y, xv[bi].y, a[oi * 4 + bi]);
                a[oi * 4 + bi] = fmaf(wv[oi].z, xv[bi].z, a[oi * 4 + bi]);
                a[oi * 4 + bi] = fmaf(wv[oi].w, xv[bi].w, a[oi * 4 + bi]);
            }
    }
#pragma unroll
    for (int off = 16; off; off >>= 1)
#pragma unroll
        for (int t = 0; t < 16; t++)
            a[t] += __shfl_xor_sync(0xffffffffu, a[t], off);
    if (lane < 16) {
        int oi = lane >> 2, bi = lane & 3;
        g_buf6[(b0 + bi) * 120 + o0 + oi] =
            fmaxf(a[lane] + __ldg(bias + o0 + oi), 0.f);
    }
}

// ---------------------------------------------------------------------------
// fc2 (relu) + fc3 fused. block per batch element.
// ---------------------------------------------------------------------------
__global__ void fc_tail_kernel(const float* __restrict__ w2,
                               const float* __restrict__ b2,
                               const float* __restrict__ w3,
                               const float* __restrict__ b3,
                               float* __restrict__ out) {
    __shared__ float h1[120];
    __shared__ float h2[84];
    int b = blockIdx.x;
    int t = threadIdx.x;
    if (t < 120) h1[t] = g_buf6[b * 120 + t];
    __syncthreads();
    if (t < 84) {
        float acc = __ldg(b2 + t);
        const float* wr = w2 + t * 120;
#pragma unroll 4
        for (int c = 0; c < 120; c++) acc = fmaf(__ldg(wr + c), h1[c], acc);
        h2[t] = fmaxf(acc, 0.0f);
    }
    __syncthreads();
    if (t < 10) {
        float acc = __ldg(b3 + t);
        const float* wr = w3 + t * 84;
#pragma unroll 4
        for (int c = 0; c < 84; c++) acc = fmaf(__ldg(wr + c), h2[c], acc);
        out[b * 10 + t] = acc;
    }
}

// ---------------------------------------------------------------------------
#define PC2_SMEM ((6240 + 44 * 224) * (int)sizeof(float))       // 64384 B
#define OO_SMEM  ((13416 + 13520) * (int)sizeof(float))         // 107744 B

extern "C" void kernel_launch(void* const* d_in, const int* in_sizes, int n_in,
                              void* d_out, int out_size) {
    const float* x     = (const float*)d_in[0];
    const float* dw1_w = (const float*)d_in[1];
    const float* dw1_b = (const float*)d_in[2];
    const float* pc1_w = (const float*)d_in[3];
    const float* pc1_b = (const float*)d_in[4];
    const float* dw2_w = (const float*)d_in[5];
    const float* dw2_b = (const float*)d_in[6];
    const float* pc2_w = (const float*)d_in[7];
    const float* pc2_b = (const float*)d_in[8];
    const float* oo_w  = (const float*)d_in[9];
    const float* oo_b  = (const float*)d_in[10];
    const float* fc1_w = (const float*)d_in[11];
    const float* fc1_b = (const float*)d_in[12];
    const float* fc2_w = (const float*)d_in[13];
    const float* fc2_b = (const float*)d_in[14];
    const float* fc3_w = (const float*)d_in[15];
    const float* fc3_b = (const float*)d_in[16];
    float* out = (float*)d_out;

    static bool attr_set = false;
    if (!attr_set) {
        cudaFuncSetAttribute(pc2pool_kernel,
                             cudaFuncAttributeMaxDynamicSharedMemorySize,
                             PC2_SMEM);
        cudaFuncSetAttribute(oo_kernel,
                             cudaFuncAttributeMaxDynamicSharedMemorySize,
                             OO_SMEM);
        attr_set = true;
    }

    init_kernel<<<148, 256>>>(pc2_w, oo_w);

    front_kernel<<<BATCH * 2, 256>>>(x, dw1_w, dw1_b, pc1_w, pc1_b);

    dw2_kernel<<<BATCH * 13, 256>>>(dw2_w, dw2_b);

    pc2pool_kernel<<<BATCH * 15, 256, PC2_SMEM>>>(pc2_b);

    oo_kernel<<<BATCH * 4, 192, OO_SMEM>>>(oo_b);

    fc1_kernel<<<60, 256>>>(fc1_w, fc1_b);

    fc_tail_kernel<<<BATCH, 128>>>(fc2_w, fc2_b, fc3_w, fc3_b, out);
}

// round 7
// speedup vs baseline: 2.7875x; 1.0003x over previous
#include <cuda_runtime.h>
#include <cuda_bf16.h>

// ---------------------------------------------------------------------------
// Net_80796924772492: small permuted-group CNN, B=64.
// front(dw1+pc1+relu+pool) -> dw2(5x5,g=51, writes padded pc2 layout)
//  -> pc2(+relu+pool, padded oo layout) -> oo 1x1 515->100 (+relu)
//  -> fc1 -> fc2 -> fc3
// ---------------------------------------------------------------------------

#define BATCH 64

__device__ float g_buf2[BATCH * 51 * 14 * 14];   // front out
__device__ float g_buf3p[BATCH * 31200];         // dw2 out, [b][py5][260ch][24]
__device__ float g_buf4[BATCH * 516 * 26];       // pc2 out, padded [516][26]
__device__ float g_buf5[BATCH * 2500];           // oo out (flattened)
__device__ float g_buf6[BATCH * 120];            // fc1 out

// pc1 per-group info: (j, rep = i*ncpf+j, base = k*ncpf, 0)
__device__ int4 g_g1info[51];
// pc2 groups sorted by k, padded to quads of 4 (same k within a quad):
// slot -> (g, j, rep = i*51+j, base = k*51). 131 quads = 524 slots.
__device__ int4 g_g2sorted[524];
// pre-padded pc2 weights: [slot 524][56] (zero pad c>=51 and dup slots)
__device__ float g_w2pad[524 * 56];
// pre-padded oo weights: [104 oc][520] zero-padded
__device__ float g_oow_pad[104 * 520];

// ---------------------------------------------------------------------------
__device__ __forceinline__ int4 group_info1(int g) {   // F=6, ncpf=3
    int rem = g, i = 0;
    for (;;) {
        int cnt = (6 - i) + 2 * (5 - i);
        if (rem < cnt) break;
        rem -= cnt; i++;
    }
    int j, k;
    if (rem < 6 - i) { j = 0; k = i + rem; }
    else { rem -= (6 - i); j = 1 + rem / (5 - i); k = i + 1 + rem % (5 - i); }
    int4 r; r.x = j; r.y = i * 3 + j; r.z = k * 3; r.w = 0;
    return r;
}

// pc2 slot decode (pure function of slot index s in [0,524))
__device__ __forceinline__ int4 slot_info2(int s) {
    const int qs[6] = {0, 1, 14, 40, 79, 131};
    const int Gk[5] = {1, 52, 103, 154, 205};
    int q = s >> 2;
    int k = 0;
    while (k < 4 && q >= qs[k + 1]) k++;
    int r = s - qs[k] * 4;
    if (r > Gk[k] - 1) r = Gk[k] - 1;       // pad: replicate last group
    int i, j;
    if (r <= k) { i = r; j = 0; }
    else { int r2 = r - (k + 1); i = r2 / 50; j = 1 + r2 % 50; }
    int base_i = 205 * i - 51 * (i * (i - 1) / 2);
    int off = (j == 0) ? (k - i) : (5 - i) + (j - 1) * (4 - i) + (k - i - 1);
    int4 v; v.x = base_i + off; v.y = j; v.z = i * 51 + j; v.w = k * 51;
    return v;
}

// ---------------------------------------------------------------------------
// init: group tables + pre-padded weight layouts + g_buf4 pad zeros.
// Work regions (grid-stride):
//  A [0,51): g1info          B [51,575): g2sorted
//  C [575,575+29344): w2pad  D: oow_pad 54080   E: g_buf4 pads 64*541
// ---------------------------------------------------------------------------
__global__ void init_kernel(const float* __restrict__ pc2_w,
                            const float* __restrict__ oo_w) {
    const int CA = 51, CB = 524, CC = 524 * 56, CD = 104 * 520, CE = 64 * 541;
    int total = CA + CB + CC + CD + CE;
    for (int t = blockIdx.x * blockDim.x + threadIdx.x; t < total;
         t += gridDim.x * blockDim.x) {
        int i = t;
        if (i < CA) { g_g1info[i] = group_info1(i); continue; }
        i -= CA;
        if (i < CB) { g_g2sorted[i] = slot_info2(i); continue; }
        i -= CB;
        if (i < CC) {
            int s = i / 56, c = i % 56;
            int g = slot_info2(s).x;
            g_w2pad[i] = (c < 51) ? __ldg(pc2_w + g * 51 + c) : 0.f;
            continue;
        }
        i -= CC;
        if (i < CD) {
            int r = i / 520, c = i % 520;
            g_oow_pad[i] = (r < 100 && c < 515) ? __ldg(oo_w + r * 515 + c) : 0.f;
            continue;
        }
        i -= CD;
        {
            int b = i / 541, r = i % 541;
            if (r < 515) g_buf4[b * 13416 + r * 26 + 25] = 0.f;
            else g_buf4[b * 13416 + 515 * 26 + (r - 515)] = 0.f;
        }
    }
}

// ---------------------------------------------------------------------------
// front: dw1 (x[64,3,32,32] -> 18x28x28 in smem) + pc1(3-ch permuted 1x1)
//        + relu + 2x2 maxpool  ->  g_buf2 [64,51,14,14].
// Block = (b, vertical half h).
// ---------------------------------------------------------------------------
__global__ void front_kernel(const float* __restrict__ x,
                             const float* __restrict__ dw1_w,
                             const float* __restrict__ dw1_b,
                             const float* __restrict__ pc1_w,
                             const float* __restrict__ pc1_b) {
    __shared__ float sx[3 * 594];    // [ch][18 rows][pitch 33]
    __shared__ float sd[18 * 396];   // [oc][14 rows][28]
    __shared__ float sw1[153];
    __shared__ float sb1[51];
    int b = blockIdx.x >> 1, h = blockIdx.x & 1;
    int r0 = h * 14;
    int tid = threadIdx.x;

    for (int i = tid; i < 3 * 576; i += 256) {
        int ch = i / 576, t = i % 576;
        int rr = t >> 5, c = t & 31;
        sx[ch * 594 + rr * 33 + c] = x[(b * 3 + ch) * 1024 + (r0 + rr) * 32 + c];
    }
    if (tid < 153) sw1[tid] = __ldg(pc1_w + tid);
    if (tid >= 160 && tid < 211) sb1[tid - 160] = __ldg(pc1_b + tid - 160);
    __syncthreads();

    for (int u = tid; u < 504; u += 256) {   // 18 oc x 14 rows x 2 halves
        int xh = u & 1;
        int t = u >> 1;
        int yol = t % 14, oc = t / 14;
        int ci = oc / 6;
        const float* wp = dw1_w + oc * 25;
        float bb = __ldg(dw1_b + oc);
        float acc[14];
#pragma unroll
        for (int q = 0; q < 14; q++) acc[q] = bb;
        for (int ky = 0; ky < 5; ky++) {
            int rb = ci * 594 + (yol + ky) * 33 + xh * 14;
            float r[18];
#pragma unroll
            for (int q = 0; q < 18; q++) r[q] = sx[rb + q];
#pragma unroll
            for (int kx = 0; kx < 5; kx++) {
                float ww = __ldg(wp + ky * 5 + kx);
#pragma unroll
                for (int xo = 0; xo < 14; xo++)
                    acc[xo] = fmaf(r[xo + kx], ww, acc[xo]);
            }
        }
        float* dst = sd + oc * 396 + yol * 28 + xh * 14;
#pragma unroll
        for (int q = 0; q < 14; q++) dst[q] = acc[q];
    }
    __syncthreads();

    for (int u = tid; u < 4998; u += 256) {  // 51 g x 7 prow x 14 px
        int px = u % 14;
        int t = u / 14;
        int pyl = t % 7, g = t / 7;
        int4 gi = g_g1info[g];
        int ch0 = (gi.x == 0) ? gi.y : gi.z + 0;
        int ch1 = (gi.x == 1) ? gi.y : gi.z + 1;
        int ch2 = (gi.x == 2) ? gi.y : gi.z + 2;
        const float* p0 = sd + ch0 * 396;
        const float* p1 = sd + ch1 * 396;
        const float* p2 = sd + ch2 * 396;
        float w0 = sw1[g * 3 + 0], w1 = sw1[g * 3 + 1], w2 = sw1[g * 3 + 2];
        float bb = sb1[g];
        float m = 0.0f;
#pragma unroll
        for (int dy = 0; dy < 2; dy++) {
#pragma unroll
            for (int dx = 0; dx < 2; dx++) {
                int off = (2 * pyl + dy) * 28 + 2 * px + dx;
                float v = bb;
                v = fmaf(w0, p0[off], v);
                v = fmaf(w1, p1[off], v);
                v = fmaf(w2, p2[off], v);
                m = fmaxf(m, v);
            }
        }
        g_buf2[((b * 51 + g) * 14 + h * 7 + pyl) * 14 + px] = m;
    }
}

// ---------------------------------------------------------------------------
// dw2: [64,51,14,14] -> padded [b][py][260ch][24]. Block=(b, 4-ch chunk)x13.
// Also zeroes pad channels 255..259 (chunk 12's spare threads).
// ---------------------------------------------------------------------------
__global__ void dw2_kernel(const float* __restrict__ w,
                           const float* __restrict__ bias) {
    __shared__ float s[4 * 200];
    int b = blockIdx.x / 13, chunk = blockIdx.x % 13;
    int c0 = chunk * 4;
    int nch = (chunk == 12) ? 3 : 4;
    int tid = threadIdx.x;
    const float* src = g_buf2 + (b * 51 + c0) * 196;
    int n = nch * 196;
    for (int i = tid; i < n; i += 256)
        s[(i / 196) * 200 + i % 196] = src[i];
    __syncthreads();

    int nu = nch * 50;
    if (tid < nu) {
        int ol = tid / 10, yo = tid % 10;
        int o = c0 * 5 + ol;
        int cil = ol / 5;
        const float* wp = w + o * 25;
        float bb = __ldg(bias + o);
        float acc[10];
#pragma unroll
        for (int t = 0; t < 10; t++) acc[t] = bb;
        for (int ky = 0; ky < 5; ky++) {
            int rb = cil * 200 + (yo + ky) * 14;
            float r[14];
#pragma unroll
            for (int t = 0; t < 14; t++) r[t] = s[rb + t];
#pragma unroll
            for (int kx = 0; kx < 5; kx++) {
                float ww = __ldg(wp + ky * 5 + kx);
#pragma unroll
                for (int xo = 0; xo < 10; xo++)
                    acc[xo] = fmaf(r[xo + kx], ww, acc[xo]);
            }
        }
        float* dst = g_buf3p + b * 31200 + (yo >> 1) * 6240 + o * 24 +
                     (yo & 1) * 12;
#pragma unroll
        for (int t = 0; t < 10; t++) dst[t] = acc[t];
        dst[10] = 0.f;
        dst[11] = 0.f;
    }
    if (chunk == 12 && tid >= 150) {
        for (int i = tid - 150; i < 600; i += 106) {
            int py = i / 120, r = i % 120;
            g_buf3p[b * 31200 + py * 6240 + 6120 + r] = 0.f;
        }
    }
}

// ---------------------------------------------------------------------------
// pc2 + relu + pool:
//   out[g] = dot51(w[g], x[k-block]) + w[g,j]*(x[rep] - x[base+j])
// Thread = (quad of 4 same-k groups, pooled px). Block = (b, py, third).
// All staging is contiguous float4 from pre-padded layouts.
// ---------------------------------------------------------------------------
__global__ void pc2pool_kernel(const float* __restrict__ bias) {
    extern __shared__ float sm[];
    float* s_in = sm;            // 6240 floats
    float* s_w = sm + 6240;      // up to 44*224 = 9856 floats
    int bid = blockIdx.x;
    int b = bid / 15;
    int t = bid % 15;
    int py = t / 3, part = t % 3;
    int q0 = part * 44;
    int nq = (part == 2) ? 43 : 44;
    int tid = threadIdx.x;

    {
        float4* si4 = (float4*)s_in;
        const float4* g4 = (const float4*)(g_buf3p + b * 31200 + py * 6240);
        for (int i = tid; i < 1560; i += 256) si4[i] = g4[i];
        float4* sw4 = (float4*)s_w;
        const float4* w4 = (const float4*)(g_w2pad + q0 * 224);
        int nf4 = nq * 56;
        for (int i = tid; i < nf4; i += 256) sw4[i] = w4[i];
    }
    __syncthreads();

    int u = tid;
    if (u < nq * 5) {
        int ql = u / 5, px = u % 5;
        int slot0 = (q0 + ql) * 4;
        int base = g_g2sorted[slot0].w;
        float a[4][4];
#pragma unroll
        for (int s2 = 0; s2 < 4; s2++)
#pragma unroll
            for (int p = 0; p < 4; p++) a[s2][p] = 0.f;
        int wb = ql * 224;
        int xb = base * 24 + 2 * px;
#pragma unroll 2
        for (int cc = 0; cc < 56; cc += 4) {
            float4 w0 = *(const float4*)&s_w[wb + cc];
            float4 w1 = *(const float4*)&s_w[wb + 56 + cc];
            float4 w2 = *(const float4*)&s_w[wb + 112 + cc];
            float4 w3 = *(const float4*)&s_w[wb + 168 + cc];
            float w0a[4] = {w0.x, w0.y, w0.z, w0.w};
            float w1a[4] = {w1.x, w1.y, w1.z, w1.w};
            float w2a[4] = {w2.x, w2.y, w2.z, w2.w};
            float w3a[4] = {w3.x, w3.y, w3.z, w3.w};
#pragma unroll
            for (int t2 = 0; t2 < 4; t2++) {
                float2 top = *(const float2*)&s_in[xb + (cc + t2) * 24];
                float2 bot = *(const float2*)&s_in[xb + (cc + t2) * 24 + 12];
                a[0][0] = fmaf(w0a[t2], top.x, a[0][0]);
                a[0][1] = fmaf(w0a[t2], top.y, a[0][1]);
                a[0][2] = fmaf(w0a[t2], bot.x, a[0][2]);
                a[0][3] = fmaf(w0a[t2], bot.y, a[0][3]);
                a[1][0] = fmaf(w1a[t2], top.x, a[1][0]);
                a[1][1] = fmaf(w1a[t2], top.y, a[1][1]);
                a[1][2] = fmaf(w1a[t2], bot.x, a[1][2]);
                a[1][3] = fmaf(w1a[t2], bot.y, a[1][3]);
                a[2][0] = fmaf(w2a[t2], top.x, a[2][0]);
                a[2][1] = fmaf(w2a[t2], top.y, a[2][1]);
                a[2][2] = fmaf(w2a[t2], bot.x, a[2][2]);
                a[2][3] = fmaf(w2a[t2], bot.y, a[2][3]);
                a[3][0] = fmaf(w3a[t2], top.x, a[3][0]);
                a[3][1] = fmaf(w3a[t2], top.y, a[3][1]);
                a[3][2] = fmaf(w3a[t2], bot.x, a[3][2]);
                a[3][3] = fmaf(w3a[t2], bot.y, a[3][3]);
            }
        }
#pragma unroll
        for (int s2 = 0; s2 < 4; s2++) {
            int4 gi = g_g2sorted[slot0 + s2];
            float wj = s_w[wb + s2 * 56 + gi.y];
            int rb2 = gi.z * 24 + 2 * px;
            int bb2 = (base + gi.y) * 24 + 2 * px;
            float2 rt = *(const float2*)&s_in[rb2];
            float2 rb_ = *(const float2*)&s_in[rb2 + 12];
            float2 bt = *(const float2*)&s_in[bb2];
            float2 bb_ = *(const float2*)&s_in[bb2 + 12];
            float v0 = fmaf(wj, rt.x - bt.x, a[s2][0]);
            float v1 = fmaf(wj, rt.y - bt.y, a[s2][1]);
            float v2 = fmaf(wj, rb_.x - bb_.x, a[s2][2]);
            float v3 = fmaf(wj, rb_.y - bb_.y, a[s2][3]);
            float m = fmaxf(fmaxf(v0, v1), fmaxf(v2, v3)) + __ldg(bias + gi.x);
            g_buf4[b * 13416 + gi.x * 26 + py * 5 + px] = fmaxf(m, 0.f);
        }
    }
}

// ---------------------------------------------------------------------------
// oo: 1x1 conv 515->100 (+relu), flattened. Block=(b, oc-quarter).
// Staging: contiguous float4 from padded layouts.
// ---------------------------------------------------------------------------
__global__ void oo_kernel(const float* __restrict__ bias) {
    extern __shared__ float sm[];
    float* xs = sm;             // [516][26]
    float* ws = sm + 13416;     // [26][520]
    int b = blockIdx.x >> 2, qo = blockIdx.x & 3;
    int tid = threadIdx.x;

    {
        float4* xs4 = (float4*)xs;
        const float4* s4 = (const float4*)(g_buf4 + b * 13416);
        for (int i = tid; i < 3354; i += 192) xs4[i] = s4[i];
        float4* ws4 = (float4*)ws;
        const float4* w4 = (const float4*)(g_oow_pad + qo * 13000);
        for (int i = tid; i < 3380; i += 192) ws4[i] = w4[i];
    }
    __syncthreads();

    if (tid < 169) {
        int ocp = tid / 13, pixp = tid % 13;
        int oc0 = 2 * ocp, pix0 = 2 * pixp;
        float a00 = 0.f, a01 = 0.f, a10 = 0.f, a11 = 0.f;
        const float* w0p = ws + oc0 * 520;
        const float* w1p = ws + (oc0 + 1) * 520;
        for (int cc = 0; cc < 516; cc += 4) {
            float4 w0 = *(const float4*)(w0p + cc);
            float4 w1 = *(const float4*)(w1p + cc);
            float w0a[4] = {w0.x, w0.y, w0.z, w0.w};
            float w1a[4] = {w1.x, w1.y, w1.z, w1.w};
#pragma unroll
            for (int t2 = 0; t2 < 4; t2++) {
                float2 xv = *(const float2*)&xs[(cc + t2) * 26 + pix0];
                a00 = fmaf(w0a[t2], xv.x, a00);
                a01 = fmaf(w0a[t2], xv.y, a01);
                a10 = fmaf(w1a[t2], xv.x, a10);
                a11 = fmaf(w1a[t2], xv.y, a11);
            }
        }
        int ocg0 = qo * 25 + oc0;
        float* dst = g_buf5 + b * 2500;
        float b0 = __ldg(bias + ocg0);
        dst[ocg0 * 25 + pix0] = fmaxf(a00 + b0, 0.f);
        if (pix0 + 1 < 25) dst[ocg0 * 25 + pix0 + 1] = fmaxf(a01 + b0, 0.f);
        if (oc0 + 1 < 25) {
            float b1 = __ldg(bias + ocg0 + 1);
            dst[(ocg0 + 1) * 25 + pix0] = fmaxf(a10 + b1, 0.f);
            if (pix0 + 1 < 25)
                dst[(ocg0 + 1) * 25 + pix0 + 1] = fmaxf(a11 + b1, 0.f);
        }
    }
}

// ---------------------------------------------------------------------------
// fc1: [64,2500] x [120,2500]^T + bias, relu. Warp tile = 4 outputs x 4 batch.
// ---------------------------------------------------------------------------
__global__ void fc1_kernel(const float* __restrict__ w,
                           const float* __restrict__ bias) {
    int wid = (blockIdx.x * blockDim.x + threadIdx.x) >> 5;
    int lane = threadIdx.x & 31;
    if (wid >= 480) return;
    int o0 = (wid / 16) * 4;
    int b0 = (wid % 16) * 4;
    const float4* w4 = (const float4*)w;
    const float4* x4 = (const float4*)g_buf5;
    float a[16];
#pragma unroll
    for (int t = 0; t < 16; t++) a[t] = 0.f;
    for (int i = lane; i < 625; i += 32) {
        float4 wv[4], xv[4];
#pragma unroll
        for (int t = 0; t < 4; t++) wv[t] = __ldg(w4 + (o0 + t) * 625 + i);
#pragma unroll
        for (int t = 0; t < 4; t++) xv[t] = x4[(b0 + t) * 625 + i];
#pragma unroll
        for (int oi = 0; oi < 4; oi++)
#pragma unroll
            for (int bi = 0; bi < 4; bi++) {
                a[oi * 4 + bi] = fmaf(wv[oi].x, xv[bi].x, a[oi * 4 + bi]);
                a[oi * 4 + bi] = fmaf(wv[oi].y, xv[bi].y, a[oi * 4 + bi]);
                a[oi * 4 + bi] = fmaf(wv[oi].z, xv[bi].z, a[oi * 4 + bi]);
                a[oi * 4 + bi] = fmaf(wv[oi].w, xv[bi].w, a[oi * 4 + bi]);
            }
    }
#pragma unroll
    for (int off = 16; off; off >>= 1)
#pragma unroll
        for (int t = 0; t < 16; t++)
            a[t] += __shfl_xor_sync(0xffffffffu, a[t], off);
    if (lane < 16) {
        int oi = lane >> 2, bi = lane & 3;
        g_buf6[(b0 + bi) * 120 + o0 + oi] =
            fmaxf(a[lane] + __ldg(bias + o0 + oi), 0.f);
    }
}

// ---------------------------------------------------------------------------
// fc2 (relu) + fc3 fused. block per batch element.
// ---------------------------------------------------------------------------
__global__ void fc_tail_kernel(const float* __restrict__ w2,
                               const float* __restrict__ b2,
                               const float* __restrict__ w3,
                               const float* __restrict__ b3,
                               float* __restrict__ out) {
    __shared__ float h1[120];
    __shared__ float h2[84];
    int b = blockIdx.x;
    int t = threadIdx.x;
    if (t < 120) h1[t] = g_buf6[b * 120 + t];
    __syncthreads();
    if (t < 84) {
        float acc = __ldg(b2 + t);
        const float* wr = w2 + t * 120;
#pragma unroll 4
        for (int c = 0; c < 120; c++) acc = fmaf(__ldg(wr + c), h1[c], acc);
        h2[t] = fmaxf(acc, 0.0f);
    }
    __syncthreads();
    if (t < 10) {
        float acc = __ldg(b3 + t);
        const float* wr = w3 + t * 84;
#pragma unroll 4
        for (int c = 0; c < 84; c++) acc = fmaf(__ldg(wr + c), h2[c], acc);
        out[b * 10 + t] = acc;
    }
}

// ---------------------------------------------------------------------------
#define PC2_SMEM ((6240 + 44 * 224) * (int)sizeof(float))       // 64384 B
#define OO_SMEM  ((13416 + 13520) * (int)sizeof(float))         // 107744 B

extern "C" void kernel_launch(void* const* d_in, const int* in_sizes, int n_in,
                              void* d_out, int out_size) {
    const float* x     = (const float*)d_in[0];
    const float* dw1_w = (const float*)d_in[1];
    const float* dw1_b = (const float*)d_in[2];
    const float* pc1_w = (const float*)d_in[3];
    const float* pc1_b = (const float*)d_in[4];
    const float* dw2_w = (const float*)d_in[5];
    const float* dw2_b = (const float*)d_in[6];
    const float* pc2_w = (const float*)d_in[7];
    const float* pc2_b = (const float*)d_in[8];
    const float* oo_w  = (const float*)d_in[9];
    const float* oo_b  = (const float*)d_in[10];
    const float* fc1_w = (const float*)d_in[11];
    const float* fc1_b = (const float*)d_in[12];
    const float* fc2_w = (const float*)d_in[13];
    const float* fc2_b = (const float*)d_in[14];
    const float* fc3_w = (const float*)d_in[15];
    const float* fc3_b = (const float*)d_in[16];
    float* out = (float*)d_out;

    static bool attr_set = false;
    if (!attr_set) {
        cudaFuncSetAttribute(pc2pool_kernel,
                             cudaFuncAttributeMaxDynamicSharedMemorySize,
                             PC2_SMEM);
        cudaFuncSetAttribute(oo_kernel,
                             cudaFuncAttributeMaxDynamicSharedMemorySize,
                             OO_SMEM);
        attr_set = true;
    }

    init_kernel<<<148, 256>>>(pc2_w, oo_w);

    front_kernel<<<BATCH * 2, 256>>>(x, dw1_w, dw1_b, pc1_w, pc1_b);

    dw2_kernel<<<BATCH * 13, 256>>>(dw2_w, dw2_b);

    pc2pool_kernel<<<BATCH * 15, 256, PC2_SMEM>>>(pc2_b);

    oo_kernel<<<BATCH * 4, 192, OO_SMEM>>>(oo_b);

    fc1_kernel<<<60, 256>>>(fc1_w, fc1_b);

    fc_tail_kernel<<<BATCH, 128>>>(fc2_w, fc2_b, fc3_w, fc3_b, out);
}